// round 1
// baseline (speedup 1.0000x reference)
#include <cuda_runtime.h>
#include <cuda_bf16.h>
#include <math_constants.h>

// Problem constants
#define BATCH 4
#define CH    256
#define HH    64
#define WW    64
#define HWN   4096          // H*W
#define MASKN 1024          // 32*32 per batch

// GEMM tiling
#define BM 128
#define BN 128
#define BK 8
#define TM 8
#define TN 8

// ---------------- scratch (device globals; no allocation allowed) ----------------
__device__ float g_wn[3][CH * CH];                         // standardized weights [which][o*C+c]
__device__ float g_qkv[3][(size_t)BATCH * CH * HWN];       // q,k,v  [which][b][c][hw]
__device__ float g_sim[(size_t)BATCH * HWN * HWN];         // sim / att, 256 MB

// ---------------- kernel 0: weight standardization ----------------
__global__ __launch_bounds__(256) void k_ws(const float* __restrict__ w,
                                            const float* __restrict__ gain,
                                            int which)
{
    const int o = blockIdx.x;
    const int t = threadIdx.x;
    const float v = w[o * CH + t];

    float s = v, ss = v * v;
#pragma unroll
    for (int off = 16; off; off >>= 1) {
        s  += __shfl_xor_sync(0xFFFFFFFFu, s,  off);
        ss += __shfl_xor_sync(0xFFFFFFFFu, ss, off);
    }
    __shared__ float sh_s[8], sh_ss[8];
    __shared__ float sh_scale, sh_msc;
    if ((t & 31) == 0) { sh_s[t >> 5] = s; sh_ss[t >> 5] = ss; }
    __syncthreads();
    if (t == 0) {
        float S = 0.f, SS = 0.f;
#pragma unroll
        for (int k = 0; k < 8; ++k) { S += sh_s[k]; SS += sh_ss[k]; }
        float mean = S * (1.0f / CH);
        float var  = (SS - (float)CH * mean * mean) * (1.0f / (CH - 1));
        float scale = rsqrtf(fmaxf(var * (float)CH, 1e-4f)) * gain[o];
        sh_scale = scale;
        sh_msc   = mean * scale;
    }
    __syncthreads();
    g_wn[which][o * CH + t] = v * sh_scale - sh_msc;
}

// ---------------- kernel 1: q/k/v = wn @ x + bias ----------------
// A = wn [256 x 256] row-major ; B = x [256 x 4096] row-major ; C = qkv
__global__ __launch_bounds__(256) void k_qkv(const float* __restrict__ aIn,
                                             const float* __restrict__ bIn,
                                             const float* __restrict__ bq,
                                             const float* __restrict__ bk,
                                             const float* __restrict__ bv)
{
    const int which = blockIdx.z >> 2;
    const int batch = blockIdx.z & 3;
    const float* __restrict__ A  = g_wn[which];
    const float* __restrict__ Bm = ((which == 1) ? bIn : aIn) + (size_t)batch * CH * HWN;
    const float* __restrict__ bias = (which == 0) ? bq : ((which == 1) ? bk : bv);
    float* __restrict__ Cm = g_qkv[which] + (size_t)batch * CH * HWN;

    const int m0 = blockIdx.y * BM;
    const int n0 = blockIdx.x * BN;

    __shared__ float As[BK][BM + 4];
    __shared__ float Bs[BK][BN + 4];

    const int tid = threadIdx.x;
    const int tx = tid & 15, ty = tid >> 4;

    const int a_row = tid >> 1;            // 0..127
    const int a_col = (tid & 1) << 2;      // 0 or 4
    const int b_row = tid >> 5;            // 0..7
    const int b_col = (tid & 31) << 2;     // 0..124

    float acc[TM][TN] = {};

    for (int k0 = 0; k0 < CH; k0 += BK) {
        float4 av = *reinterpret_cast<const float4*>(&A[(m0 + a_row) * CH + k0 + a_col]);
        As[a_col + 0][a_row] = av.x;
        As[a_col + 1][a_row] = av.y;
        As[a_col + 2][a_row] = av.z;
        As[a_col + 3][a_row] = av.w;
        *reinterpret_cast<float4*>(&Bs[b_row][b_col]) =
            *reinterpret_cast<const float4*>(&Bm[(size_t)(k0 + b_row) * HWN + n0 + b_col]);
        __syncthreads();
#pragma unroll
        for (int kk = 0; kk < BK; ++kk) {
            float4 a0 = *reinterpret_cast<const float4*>(&As[kk][ty * TM]);
            float4 a1 = *reinterpret_cast<const float4*>(&As[kk][ty * TM + 4]);
            float4 b0 = *reinterpret_cast<const float4*>(&Bs[kk][tx * TN]);
            float4 b1 = *reinterpret_cast<const float4*>(&Bs[kk][tx * TN + 4]);
            float af[TM] = {a0.x, a0.y, a0.z, a0.w, a1.x, a1.y, a1.z, a1.w};
            float bf[TN] = {b0.x, b0.y, b0.z, b0.w, b1.x, b1.y, b1.z, b1.w};
#pragma unroll
            for (int r = 0; r < TM; ++r)
#pragma unroll
                for (int s = 0; s < TN; ++s)
                    acc[r][s] += af[r] * bf[s];
        }
        __syncthreads();
    }

#pragma unroll
    for (int r = 0; r < TM; ++r) {
        const int m = m0 + ty * TM + r;
        const float bb = bias[m];
#pragma unroll
        for (int s = 0; s < TN; s += 4) {
            float4 o;
            o.x = acc[r][s + 0] + bb;
            o.y = acc[r][s + 1] + bb;
            o.z = acc[r][s + 2] + bb;
            o.w = acc[r][s + 3] + bb;
            *reinterpret_cast<float4*>(&Cm[(size_t)m * HWN + n0 + tx * TN + s]) = o;
        }
    }
}

// ---------------- kernel 2: sim = q^T k ----------------
// A[m=i][k=c] = q[c*HW + i] (contiguous in m) ; B[k=c][n=j] = k[c*HW + j]
__global__ __launch_bounds__(256) void k_sim()
{
    const int batch = blockIdx.z;
    const float* __restrict__ Q  = g_qkv[0] + (size_t)batch * CH * HWN;
    const float* __restrict__ Kt = g_qkv[1] + (size_t)batch * CH * HWN;
    float* __restrict__ S = g_sim + (size_t)batch * HWN * HWN;

    const int m0 = blockIdx.y * BM;
    const int n0 = blockIdx.x * BN;

    __shared__ float As[BK][BM + 4];
    __shared__ float Bs[BK][BN + 4];

    const int tid = threadIdx.x;
    const int tx = tid & 15, ty = tid >> 4;

    const int a_kk = tid >> 5;             // 0..7
    const int a_mm = (tid & 31) << 2;      // 0..124
    const int b_row = tid >> 5;
    const int b_col = (tid & 31) << 2;

    float acc[TM][TN] = {};

    for (int k0 = 0; k0 < CH; k0 += BK) {
        *reinterpret_cast<float4*>(&As[a_kk][a_mm]) =
            *reinterpret_cast<const float4*>(&Q[(size_t)(k0 + a_kk) * HWN + m0 + a_mm]);
        *reinterpret_cast<float4*>(&Bs[b_row][b_col]) =
            *reinterpret_cast<const float4*>(&Kt[(size_t)(k0 + b_row) * HWN + n0 + b_col]);
        __syncthreads();
#pragma unroll
        for (int kk = 0; kk < BK; ++kk) {
            float4 a0 = *reinterpret_cast<const float4*>(&As[kk][ty * TM]);
            float4 a1 = *reinterpret_cast<const float4*>(&As[kk][ty * TM + 4]);
            float4 b0 = *reinterpret_cast<const float4*>(&Bs[kk][tx * TN]);
            float4 b1 = *reinterpret_cast<const float4*>(&Bs[kk][tx * TN + 4]);
            float af[TM] = {a0.x, a0.y, a0.z, a0.w, a1.x, a1.y, a1.z, a1.w};
            float bf[TN] = {b0.x, b0.y, b0.z, b0.w, b1.x, b1.y, b1.z, b1.w};
#pragma unroll
            for (int r = 0; r < TM; ++r)
#pragma unroll
                for (int s = 0; s < TN; ++s)
                    acc[r][s] += af[r] * bf[s];
        }
        __syncthreads();
    }

#pragma unroll
    for (int r = 0; r < TM; ++r) {
        const int m = m0 + ty * TM + r;
#pragma unroll
        for (int s = 0; s < TN; s += 4) {
            float4 o;
            o.x = acc[r][s + 0];
            o.y = acc[r][s + 1];
            o.z = acc[r][s + 2];
            o.w = acc[r][s + 3];
            *reinterpret_cast<float4*>(&S[(size_t)m * HWN + n0 + tx * TN + s]) = o;
        }
    }
}

// ---------------- kernel 3: masked softmax over rows (in place) ----------------
__global__ __launch_bounds__(256) void k_softmax(const float* __restrict__ cIn)
{
    const int i = blockIdx.x;
    const int batch = blockIdx.y;
    float* __restrict__ row = g_sim + ((size_t)batch * HWN + i) * HWN;

    const int h = i >> 6, w = i & 63;
    const float m = cIn[batch * MASKN + (h >> 1) * 32 + (w >> 1)];

    const int tid = threadIdx.x;
    float x[16];
    float vmax = -CUDART_INF_F;
#pragma unroll
    for (int p = 0; p < 4; ++p) {
        float4 v = *reinterpret_cast<const float4*>(&row[(p * 256 + tid) * 4]);
        x[p * 4 + 0] = m * v.x;
        x[p * 4 + 1] = m * v.y;
        x[p * 4 + 2] = m * v.z;
        x[p * 4 + 3] = m * v.w;
#pragma unroll
        for (int q = 0; q < 4; ++q) vmax = fmaxf(vmax, x[p * 4 + q]);
    }

    __shared__ float redm[8], reds[8];
    __shared__ float sh_max, sh_sum;
#pragma unroll
    for (int off = 16; off; off >>= 1) vmax = fmaxf(vmax, __shfl_xor_sync(0xFFFFFFFFu, vmax, off));
    if ((tid & 31) == 0) redm[tid >> 5] = vmax;
    __syncthreads();
    if (tid == 0) {
        float v = redm[0];
#pragma unroll
        for (int k = 1; k < 8; ++k) v = fmaxf(v, redm[k]);
        sh_max = v;
    }
    __syncthreads();
    const float M = sh_max;

    float total = 0.f;
#pragma unroll
    for (int q = 0; q < 16; ++q) {
        float e = __expf(x[q] - M);
        x[q] = e;
        total += e;
    }
#pragma unroll
    for (int off = 16; off; off >>= 1) total += __shfl_xor_sync(0xFFFFFFFFu, total, off);
    if ((tid & 31) == 0) reds[tid >> 5] = total;
    __syncthreads();
    if (tid == 0) {
        float v = 0.f;
#pragma unroll
        for (int k = 0; k < 8; ++k) v += reds[k];
        sh_sum = v;
    }
    __syncthreads();
    const float inv = 1.0f / sh_sum;

#pragma unroll
    for (int p = 0; p < 4; ++p) {
        float4 v;
        v.x = x[p * 4 + 0] * inv;
        v.y = x[p * 4 + 1] * inv;
        v.z = x[p * 4 + 2] * inv;
        v.w = x[p * 4 + 3] * inv;
        *reinterpret_cast<float4*>(&row[(p * 256 + tid) * 4]) = v;
    }
}

// ---------------- kernel 4: out = v @ att^T, fused final blend ----------------
// A = v [256 x 4096] row-major ; B[k=j][n=i] = att[i*HW + j] (contiguous in k)
__global__ __launch_bounds__(256) void k_out(const float* __restrict__ aIn,
                                             const float* __restrict__ cIn,
                                             const float* __restrict__ gammaPtr,
                                             float* __restrict__ out)
{
    const int batch = blockIdx.z;
    const float* __restrict__ V   = g_qkv[2] + (size_t)batch * CH * HWN;
    const float* __restrict__ Att = g_sim + (size_t)batch * HWN * HWN;

    const int m0 = blockIdx.y * BM;   // c
    const int n0 = blockIdx.x * BN;   // i

    __shared__ float As[BK][BM + 4];
    __shared__ float Bs[BK][BN + 4];

    const int tid = threadIdx.x;
    const int tx = tid & 15, ty = tid >> 4;

    const int a_row = tid >> 1;
    const int a_col = (tid & 1) << 2;
    const int b_n   = tid >> 1;
    const int b_k   = (tid & 1) << 2;

    float acc[TM][TN] = {};

    for (int k0 = 0; k0 < HWN; k0 += BK) {
        float4 av = *reinterpret_cast<const float4*>(&V[(size_t)(m0 + a_row) * HWN + k0 + a_col]);
        As[a_col + 0][a_row] = av.x;
        As[a_col + 1][a_row] = av.y;
        As[a_col + 2][a_row] = av.z;
        As[a_col + 3][a_row] = av.w;
        float4 bv4 = *reinterpret_cast<const float4*>(&Att[(size_t)(n0 + b_n) * HWN + k0 + b_k]);
        Bs[b_k + 0][b_n] = bv4.x;
        Bs[b_k + 1][b_n] = bv4.y;
        Bs[b_k + 2][b_n] = bv4.z;
        Bs[b_k + 3][b_n] = bv4.w;
        __syncthreads();
#pragma unroll
        for (int kk = 0; kk < BK; ++kk) {
            float4 a0 = *reinterpret_cast<const float4*>(&As[kk][ty * TM]);
            float4 a1 = *reinterpret_cast<const float4*>(&As[kk][ty * TM + 4]);
            float4 b0 = *reinterpret_cast<const float4*>(&Bs[kk][tx * TN]);
            float4 b1 = *reinterpret_cast<const float4*>(&Bs[kk][tx * TN + 4]);
            float af[TM] = {a0.x, a0.y, a0.z, a0.w, a1.x, a1.y, a1.z, a1.w};
            float bf[TN] = {b0.x, b0.y, b0.z, b0.w, b1.x, b1.y, b1.z, b1.w};
#pragma unroll
            for (int r = 0; r < TM; ++r)
#pragma unroll
                for (int s = 0; s < TN; ++s)
                    acc[r][s] += af[r] * bf[s];
        }
        __syncthreads();
    }

    const float gamma = gammaPtr[0];
#pragma unroll
    for (int r = 0; r < TM; ++r) {
        const int cc = m0 + ty * TM + r;
        const size_t base = ((size_t)batch * CH + cc) * HWN;
#pragma unroll
        for (int s = 0; s < TN; s += 4) {
            const int i0 = n0 + tx * TN + s;
            float4 av = *reinterpret_cast<const float4*>(&aIn[base + i0]);
            float4 o;
#pragma unroll
            for (int q = 0; q < 4; ++q) {
                const int i = i0 + q;
                const int h = i >> 6, w = i & 63;
                const float cr = cIn[batch * MASKN + (h >> 1) * 32 + (w >> 1)];
                const float aval = (q == 0) ? av.x : (q == 1) ? av.y : (q == 2) ? av.z : av.w;
                const float y = aval * cr + gamma * (1.0f - cr) * acc[r][s + q];
                ((float*)&o)[q] = y;
            }
            *reinterpret_cast<float4*>(&out[base + i0]) = o;
        }
    }
}

// ---------------- launch ----------------
extern "C" void kernel_launch(void* const* d_in, const int* in_sizes, int n_in,
                              void* d_out, int out_size)
{
    const float* a     = (const float*)d_in[0];
    const float* b     = (const float*)d_in[1];
    const float* cmask = (const float*)d_in[2];
    const float* wq    = (const float*)d_in[3];
    const float* bq    = (const float*)d_in[4];
    const float* gq    = (const float*)d_in[5];
    const float* wk    = (const float*)d_in[6];
    const float* bk    = (const float*)d_in[7];
    const float* gk    = (const float*)d_in[8];
    const float* wv    = (const float*)d_in[9];
    const float* bv    = (const float*)d_in[10];
    const float* gv    = (const float*)d_in[11];
    const float* gamma = (const float*)d_in[12];
    float* out = (float*)d_out;

    k_ws<<<CH, 256>>>(wq, gq, 0);
    k_ws<<<CH, 256>>>(wk, gk, 1);
    k_ws<<<CH, 256>>>(wv, gv, 2);

    dim3 g1(HWN / BN, CH / BM, 12);        // 32 x 2 x 12
    k_qkv<<<g1, 256>>>(a, b, bq, bk, bv);

    dim3 g2(HWN / BN, HWN / BM, BATCH);    // 32 x 32 x 4
    k_sim<<<g2, 256>>>();

    k_softmax<<<dim3(HWN, BATCH), 256>>>(cmask);

    dim3 g4(HWN / BN, CH / BM, BATCH);     // 32 x 2 x 4
    k_out<<<g4, 256>>>(a, cmask, gamma, out);
}

// round 5
// speedup vs baseline: 1.8883x; 1.8883x over previous
#include <cuda_runtime.h>
#include <cuda_bf16.h>
#include <math_constants.h>
#include <cstdint>

#define BATCH 4
#define CH    256
#define HWN   4096
#define MASKN 1024

// SIMT GEMM tiling (qkv kernels)
#define BM 128
#define BN 128
#define BK 8
#define TM 8
#define TN 8

// ---------------- scratch ----------------
__device__ float g_wn[3][CH * CH];
__device__ __nv_bfloat16 g_qT_hi[(size_t)BATCH * HWN * CH];
__device__ __nv_bfloat16 g_qT_lo[(size_t)BATCH * HWN * CH];
__device__ __nv_bfloat16 g_kT_hi[(size_t)BATCH * HWN * CH];
__device__ __nv_bfloat16 g_kT_lo[(size_t)BATCH * HWN * CH];
__device__ __nv_bfloat16 g_v_hi[(size_t)BATCH * CH * HWN];
__device__ __nv_bfloat16 g_v_lo[(size_t)BATCH * CH * HWN];
__device__ float g_sim[(size_t)BATCH * HWN * HWN];
__device__ __nv_bfloat16 g_att_hi[(size_t)BATCH * HWN * HWN];
__device__ __nv_bfloat16 g_att_lo[(size_t)BATCH * HWN * HWN];

// ---------------- helpers ----------------
__device__ __forceinline__ uint32_t smem_u32(const void* p) {
    uint32_t a;
    asm("{ .reg .u64 t; cvta.to.shared.u64 t, %1; cvt.u32.u64 %0, t; }" : "=r"(a) : "l"(p));
    return a;
}
__device__ __forceinline__ void cp16(uint32_t dst, const void* src) {
    asm volatile("cp.async.cg.shared.global [%0], [%1], 16;" :: "r"(dst), "l"(src));
}
#define CP_COMMIT() asm volatile("cp.async.commit_group;")
#define CP_WAIT1()  asm volatile("cp.async.wait_group 1;")
#define CP_WAIT0()  asm volatile("cp.async.wait_group 0;")

__device__ __forceinline__ void ldsm_x4(uint32_t addr, uint32_t r[4]) {
    asm volatile("ldmatrix.sync.aligned.m8n8.x4.shared.b16 {%0,%1,%2,%3}, [%4];"
                 : "=r"(r[0]), "=r"(r[1]), "=r"(r[2]), "=r"(r[3]) : "r"(addr));
}
__device__ __forceinline__ void mma16816(float c[4], const uint32_t a[4], const uint32_t b[2]) {
    asm volatile("mma.sync.aligned.m16n8k16.row.col.f32.bf16.bf16.f32 "
                 "{%0,%1,%2,%3}, {%4,%5,%6,%7}, {%8,%9}, {%0,%1,%2,%3};"
                 : "+f"(c[0]), "+f"(c[1]), "+f"(c[2]), "+f"(c[3])
                 : "r"(a[0]), "r"(a[1]), "r"(a[2]), "r"(a[3]), "r"(b[0]), "r"(b[1]));
}

// tile layout: 128 rows x 32 bytes (16 bf16), swizzled so ldmatrix is conflict-free
__device__ __forceinline__ uint32_t swoff(int row, int seg) {
    return (uint32_t)row * 32 + ((seg ^ ((row >> 2) & 1)) << 4);
}

#define TILE16B 4096                     // 128 x 32B
// stage buffers: [stage][tile(Ah,Al,Bh,Bl)][4KB]
struct MmaSmem { char buf[2][4][TILE16B]; };

// cp one 128x16 bf16 tile (4KB) with 256 threads (one 16B per thread)
__device__ __forceinline__ void cp_tile16(uint32_t sdst, const __nv_bfloat16* g,
                                          size_t ld, int row0, int k0) {
    const int t = threadIdx.x;
    const int row = t >> 1;
    const int seg = t & 1;
    const char* src = reinterpret_cast<const char*>(g + (size_t)(row0 + row) * ld + k0 + seg * 8);
    cp16(sdst + swoff(row, seg), src);
}

__device__ __forceinline__ void load_stage16(uint32_t sb,
    const __nv_bfloat16* Ah, const __nv_bfloat16* Al, size_t lda, int m0,
    const __nv_bfloat16* Bh, const __nv_bfloat16* Bl, size_t ldb, int n0, int k0)
{
    cp_tile16(sb,               Ah, lda, m0, k0);
    cp_tile16(sb + TILE16B,     Al, lda, m0, k0);
    cp_tile16(sb + 2 * TILE16B, Bh, ldb, n0, k0);
    cp_tile16(sb + 3 * TILE16B, Bl, ldb, n0, k0);
}

// one k=16 slice: acc += Ah*Bh + Ah*Bl + Al*Bh   (warp tile 32x64)
__device__ __forceinline__ void compute_stage16(uint32_t sb, float acc[2][8][4],
                                                int lane, int wm, int wn)
{
    const uint32_t sAh = sb, sAl = sb + TILE16B, sBh = sb + 2 * TILE16B, sBl = sb + 3 * TILE16B;
    uint32_t ah[2][4], al[2][4];
    const int aseg = lane >> 4;
#pragma unroll
    for (int mt = 0; mt < 2; ++mt) {
        const int arow = wm * 32 + mt * 16 + (lane & 15);
        ldsm_x4(sAh + swoff(arow, aseg), ah[mt]);
        ldsm_x4(sAl + swoff(arow, aseg), al[mt]);
    }
    const int brow_in = ((lane >> 4) << 3) + (lane & 7);
    const int bseg = (lane >> 3) & 1;
#pragma unroll
    for (int ntp = 0; ntp < 4; ++ntp) {
        const int brow = wn * 64 + ntp * 16 + brow_in;
        uint32_t bh[4], bl[4];
        ldsm_x4(sBh + swoff(brow, bseg), bh);
        ldsm_x4(sBl + swoff(brow, bseg), bl);
#pragma unroll
        for (int mt = 0; mt < 2; ++mt) {
#pragma unroll
            for (int h = 0; h < 2; ++h) {
                const int nt = ntp * 2 + h;
                mma16816(acc[mt][nt], ah[mt], bh + h * 2);
                mma16816(acc[mt][nt], ah[mt], bl + h * 2);
                mma16816(acc[mt][nt], al[mt], bh + h * 2);
            }
        }
    }
}

// C[128x128] += A[m0..+128, :k] * B[n0..+128, :k]^T (both [row][k], 3-term hi/lo)
__device__ __forceinline__ void gemm_hilo(uint32_t sb0,
    const __nv_bfloat16* Ah, const __nv_bfloat16* Al, size_t lda, int m0,
    const __nv_bfloat16* Bh, const __nv_bfloat16* Bl, size_t ldb, int n0,
    int kTotal, float acc[2][8][4])
{
    const int lane = threadIdx.x & 31;
    const int w = threadIdx.x >> 5;
    const int wm = w & 3, wn = w >> 2;
    const int nk = kTotal / 16;

    load_stage16(sb0, Ah, Al, lda, m0, Bh, Bl, ldb, n0, 0);
    CP_COMMIT();
    for (int kc = 0; kc < nk; ++kc) {
        if (kc + 1 < nk) {
            load_stage16(sb0 + ((kc + 1) & 1) * (4 * TILE16B),
                         Ah, Al, lda, m0, Bh, Bl, ldb, n0, (kc + 1) * 16);
            CP_COMMIT();
            CP_WAIT1();
        } else {
            CP_WAIT0();
        }
        __syncthreads();
        compute_stage16(sb0 + (kc & 1) * (4 * TILE16B), acc, lane, wm, wn);
        __syncthreads();
    }
}

// ---------------- kernel 0: weight standardization ----------------
__global__ __launch_bounds__(256) void k_ws(const float* __restrict__ w,
                                            const float* __restrict__ gain, int which)
{
    const int o = blockIdx.x;
    const int t = threadIdx.x;
    const float v = w[o * CH + t];
    float s = v, ss = v * v;
#pragma unroll
    for (int off = 16; off; off >>= 1) {
        s  += __shfl_xor_sync(0xFFFFFFFFu, s,  off);
        ss += __shfl_xor_sync(0xFFFFFFFFu, ss, off);
    }
    __shared__ float sh_s[8], sh_ss[8], sh_scale, sh_msc;
    if ((t & 31) == 0) { sh_s[t >> 5] = s; sh_ss[t >> 5] = ss; }
    __syncthreads();
    if (t == 0) {
        float S = 0.f, SS = 0.f;
#pragma unroll
        for (int k = 0; k < 8; ++k) { S += sh_s[k]; SS += sh_ss[k]; }
        float mean = S * (1.0f / CH);
        float var  = (SS - (float)CH * mean * mean) * (1.0f / (CH - 1));
        float scale = rsqrtf(fmaxf(var * (float)CH, 1e-4f)) * gain[o];
        sh_scale = scale;
        sh_msc   = mean * scale;
    }
    __syncthreads();
    g_wn[which][o * CH + t] = v * sh_scale - sh_msc;
}

// ---------------- kernel 1: qT/kT = x^T @ wn^T, bf16 hi/lo, [hw][c] ----------------
__global__ __launch_bounds__(256) void k_qkT(const float* __restrict__ aIn,
                                             const float* __restrict__ bIn,
                                             const float* __restrict__ bq,
                                             const float* __restrict__ bk)
{
    const int which = blockIdx.z >> 2;
    const int batch = blockIdx.z & 3;
    const float* __restrict__ X = ((which == 1) ? bIn : aIn) + (size_t)batch * CH * HWN;
    const float* __restrict__ Wn = g_wn[which];
    const float* __restrict__ bias = which ? bk : bq;
    __nv_bfloat16* __restrict__ Hi = (which ? g_kT_hi : g_qT_hi) + (size_t)batch * HWN * CH;
    __nv_bfloat16* __restrict__ Lo = (which ? g_kT_lo : g_qT_lo) + (size_t)batch * HWN * CH;

    const int m0 = blockIdx.y * BM;   // hw
    const int n0 = blockIdx.x * BN;   // co

    __shared__ float As[BK][BM + 4];
    __shared__ float Bs[BK][BN + 4];

    const int tid = threadIdx.x;
    const int tx = tid & 15, ty = tid >> 4;
    const int a_kk = tid >> 5, a_mm = (tid & 31) << 2;
    const int b_n = tid >> 1, b_k = (tid & 1) << 2;

    float acc[TM][TN] = {};
    for (int k0 = 0; k0 < CH; k0 += BK) {
        *reinterpret_cast<float4*>(&As[a_kk][a_mm]) =
            *reinterpret_cast<const float4*>(&X[(size_t)(k0 + a_kk) * HWN + m0 + a_mm]);
        float4 bv4 = *reinterpret_cast<const float4*>(&Wn[(n0 + b_n) * CH + k0 + b_k]);
        Bs[b_k + 0][b_n] = bv4.x;
        Bs[b_k + 1][b_n] = bv4.y;
        Bs[b_k + 2][b_n] = bv4.z;
        Bs[b_k + 3][b_n] = bv4.w;
        __syncthreads();
#pragma unroll
        for (int kk = 0; kk < BK; ++kk) {
            float4 a0 = *reinterpret_cast<const float4*>(&As[kk][ty * TM]);
            float4 a1 = *reinterpret_cast<const float4*>(&As[kk][ty * TM + 4]);
            float4 b0 = *reinterpret_cast<const float4*>(&Bs[kk][tx * TN]);
            float4 b1 = *reinterpret_cast<const float4*>(&Bs[kk][tx * TN + 4]);
            float af[TM] = {a0.x, a0.y, a0.z, a0.w, a1.x, a1.y, a1.z, a1.w};
            float bf[TN] = {b0.x, b0.y, b0.z, b0.w, b1.x, b1.y, b1.z, b1.w};
#pragma unroll
            for (int r = 0; r < TM; ++r)
#pragma unroll
                for (int s = 0; s < TN; ++s)
                    acc[r][s] += af[r] * bf[s];
        }
        __syncthreads();
    }

#pragma unroll
    for (int r = 0; r < TM; ++r) {
        const int m = m0 + ty * TM + r;
        const size_t rowb = (size_t)m * CH + n0 + tx * TN;
#pragma unroll
        for (int s = 0; s < TN; s += 2) {
            float v0 = acc[r][s]     + bias[n0 + tx * TN + s];
            float v1 = acc[r][s + 1] + bias[n0 + tx * TN + s + 1];
            __nv_bfloat16 h0 = __float2bfloat16_rn(v0);
            __nv_bfloat16 h1 = __float2bfloat16_rn(v1);
            __nv_bfloat16 l0 = __float2bfloat16_rn(v0 - __bfloat162float(h0));
            __nv_bfloat16 l1 = __float2bfloat16_rn(v1 - __bfloat162float(h1));
            *reinterpret_cast<__nv_bfloat162*>(&Hi[rowb + s]) = __nv_bfloat162(h0, h1);
            *reinterpret_cast<__nv_bfloat162*>(&Lo[rowb + s]) = __nv_bfloat162(l0, l1);
        }
    }
}

// ---------------- kernel 2: v = wn @ x, bf16 hi/lo, [c][hw] ----------------
__global__ __launch_bounds__(256) void k_v(const float* __restrict__ aIn,
                                           const float* __restrict__ bv)
{
    const int batch = blockIdx.z;
    const float* __restrict__ A  = g_wn[2];
    const float* __restrict__ Bm = aIn + (size_t)batch * CH * HWN;
    __nv_bfloat16* __restrict__ Hi = g_v_hi + (size_t)batch * CH * HWN;
    __nv_bfloat16* __restrict__ Lo = g_v_lo + (size_t)batch * CH * HWN;

    const int m0 = blockIdx.y * BM;
    const int n0 = blockIdx.x * BN;

    __shared__ float As[BK][BM + 4];
    __shared__ float Bs[BK][BN + 4];

    const int tid = threadIdx.x;
    const int tx = tid & 15, ty = tid >> 4;
    const int a_row = tid >> 1, a_col = (tid & 1) << 2;
    const int b_row = tid >> 5, b_col = (tid & 31) << 2;

    float acc[TM][TN] = {};
    for (int k0 = 0; k0 < CH; k0 += BK) {
        float4 av = *reinterpret_cast<const float4*>(&A[(m0 + a_row) * CH + k0 + a_col]);
        As[a_col + 0][a_row] = av.x;
        As[a_col + 1][a_row] = av.y;
        As[a_col + 2][a_row] = av.z;
        As[a_col + 3][a_row] = av.w;
        *reinterpret_cast<float4*>(&Bs[b_row][b_col]) =
            *reinterpret_cast<const float4*>(&Bm[(size_t)(k0 + b_row) * HWN + n0 + b_col]);
        __syncthreads();
#pragma unroll
        for (int kk = 0; kk < BK; ++kk) {
            float4 a0 = *reinterpret_cast<const float4*>(&As[kk][ty * TM]);
            float4 a1 = *reinterpret_cast<const float4*>(&As[kk][ty * TM + 4]);
            float4 b0 = *reinterpret_cast<const float4*>(&Bs[kk][tx * TN]);
            float4 b1 = *reinterpret_cast<const float4*>(&Bs[kk][tx * TN + 4]);
            float af[TM] = {a0.x, a0.y, a0.z, a0.w, a1.x, a1.y, a1.z, a1.w};
            float bf[TN] = {b0.x, b0.y, b0.z, b0.w, b1.x, b1.y, b1.z, b1.w};
#pragma unroll
            for (int r = 0; r < TM; ++r)
#pragma unroll
                for (int s = 0; s < TN; ++s)
                    acc[r][s] += af[r] * bf[s];
        }
        __syncthreads();
    }

#pragma unroll
    for (int r = 0; r < TM; ++r) {
        const int m = m0 + ty * TM + r;
        const float bb = bv[m];
        const size_t rowb = (size_t)m * HWN + n0 + tx * TN;
#pragma unroll
        for (int s = 0; s < TN; s += 2) {
            float v0 = acc[r][s] + bb;
            float v1 = acc[r][s + 1] + bb;
            __nv_bfloat16 h0 = __float2bfloat16_rn(v0);
            __nv_bfloat16 h1 = __float2bfloat16_rn(v1);
            __nv_bfloat16 l0 = __float2bfloat16_rn(v0 - __bfloat162float(h0));
            __nv_bfloat16 l1 = __float2bfloat16_rn(v1 - __bfloat162float(h1));
            *reinterpret_cast<__nv_bfloat162*>(&Hi[rowb + s]) = __nv_bfloat162(h0, h1);
            *reinterpret_cast<__nv_bfloat162*>(&Lo[rowb + s]) = __nv_bfloat162(l0, l1);
        }
    }
}

// ---------------- kernel 3: sim = qT @ kT^T (mma.sync) ----------------
__global__ __launch_bounds__(256) void k_sim_mma()
{
    __shared__ __align__(1024) MmaSmem sm;
    const uint32_t sb0 = smem_u32(&sm);

    const int batch = blockIdx.z;
    const int m0 = blockIdx.y * 128;
    const int n0 = blockIdx.x * 128;
    const size_t boff = (size_t)batch * HWN * CH;

    float acc[2][8][4] = {};
    gemm_hilo(sb0, g_qT_hi + boff, g_qT_lo + boff, CH, m0,
              g_kT_hi + boff, g_kT_lo + boff, CH, n0, CH, acc);

    float* __restrict__ S = g_sim + (size_t)batch * HWN * HWN;
    const int lane = threadIdx.x & 31;
    const int w = threadIdx.x >> 5;
    const int wm = w & 3, wn = w >> 2;
    const int gm_base = m0 + wm * 32 + (lane >> 2);
    const int gn_base = n0 + wn * 64 + (lane & 3) * 2;
#pragma unroll
    for (int mt = 0; mt < 2; ++mt) {
#pragma unroll
        for (int nt = 0; nt < 8; ++nt) {
            const int gm = gm_base + mt * 16;
            const int gn = gn_base + nt * 8;
            float2 p0 = {acc[mt][nt][0], acc[mt][nt][1]};
            float2 p1 = {acc[mt][nt][2], acc[mt][nt][3]};
            *reinterpret_cast<float2*>(&S[(size_t)gm * HWN + gn]) = p0;
            *reinterpret_cast<float2*>(&S[(size_t)(gm + 8) * HWN + gn]) = p1;
        }
    }
}

// ---------------- kernel 4: masked softmax -> att bf16 hi/lo ----------------
__global__ __launch_bounds__(256) void k_softmax(const float* __restrict__ cIn)
{
    const int i = blockIdx.x;
    const int batch = blockIdx.y;
    const float* __restrict__ row = g_sim + ((size_t)batch * HWN + i) * HWN;
    __nv_bfloat16* __restrict__ Hi = g_att_hi + ((size_t)batch * HWN + i) * HWN;
    __nv_bfloat16* __restrict__ Lo = g_att_lo + ((size_t)batch * HWN + i) * HWN;

    const int h = i >> 6, w = i & 63;
    const float m = cIn[batch * MASKN + (h >> 1) * 32 + (w >> 1)];

    const int tid = threadIdx.x;
    float x[16];
    float vmax = -CUDART_INF_F;
#pragma unroll
    for (int p = 0; p < 4; ++p) {
        float4 v = *reinterpret_cast<const float4*>(&row[(p * 256 + tid) * 4]);
        x[p * 4 + 0] = m * v.x; x[p * 4 + 1] = m * v.y;
        x[p * 4 + 2] = m * v.z; x[p * 4 + 3] = m * v.w;
#pragma unroll
        for (int q = 0; q < 4; ++q) vmax = fmaxf(vmax, x[p * 4 + q]);
    }

    __shared__ float redm[8], reds[8], sh_max, sh_sum;
#pragma unroll
    for (int off = 16; off; off >>= 1) vmax = fmaxf(vmax, __shfl_xor_sync(0xFFFFFFFFu, vmax, off));
    if ((tid & 31) == 0) redm[tid >> 5] = vmax;
    __syncthreads();
    if (tid == 0) {
        float v = redm[0];
#pragma unroll
        for (int k = 1; k < 8; ++k) v = fmaxf(v, redm[k]);
        sh_max = v;
    }
    __syncthreads();
    const float M = sh_max;

    float total = 0.f;
#pragma unroll
    for (int q = 0; q < 16; ++q) {
        float e = __expf(x[q] - M);
        x[q] = e;
        total += e;
    }
#pragma unroll
    for (int off = 16; off; off >>= 1) total += __shfl_xor_sync(0xFFFFFFFFu, total, off);
    if ((tid & 31) == 0) reds[tid >> 5] = total;
    __syncthreads();
    if (tid == 0) {
        float v = 0.f;
#pragma unroll
        for (int k = 0; k < 8; ++k) v += reds[k];
        sh_sum = v;
    }
    __syncthreads();
    const float inv = 1.0f / sh_sum;

#pragma unroll
    for (int p = 0; p < 4; ++p) {
        const int idx = (p * 256 + tid) * 4;
#pragma unroll
        for (int q = 0; q < 4; q += 2) {
            float v0 = x[p * 4 + q] * inv;
            float v1 = x[p * 4 + q + 1] * inv;
            __nv_bfloat16 h0 = __float2bfloat16_rn(v0);
            __nv_bfloat16 h1 = __float2bfloat16_rn(v1);
            __nv_bfloat16 l0 = __float2bfloat16_rn(v0 - __bfloat162float(h0));
            __nv_bfloat16 l1 = __float2bfloat16_rn(v1 - __bfloat162float(h1));
            *reinterpret_cast<__nv_bfloat162*>(&Hi[idx + q]) = __nv_bfloat162(h0, h1);
            *reinterpret_cast<__nv_bfloat162*>(&Lo[idx + q]) = __nv_bfloat162(l0, l1);
        }
    }
}

// ---------------- kernel 5: out = v @ att^T (mma.sync), fused blend ----------------
__global__ __launch_bounds__(256) void k_pv_mma(const float* __restrict__ aIn,
                                                const float* __restrict__ cIn,
                                                const float* __restrict__ gammaPtr,
                                                float* __restrict__ out)
{
    __shared__ __align__(1024) MmaSmem sm;
    const uint32_t sb0 = smem_u32(&sm);

    const int batch = blockIdx.z;
    const int m0 = blockIdx.y * 128;   // channel
    const int n0 = blockIdx.x * 128;   // position i
    const size_t voff = (size_t)batch * CH * HWN;
    const size_t aoff = (size_t)batch * HWN * HWN;

    float acc[2][8][4] = {};
    gemm_hilo(sb0, g_v_hi + voff, g_v_lo + voff, HWN, m0,
              g_att_hi + aoff, g_att_lo + aoff, HWN, n0, HWN, acc);

    const float gamma = gammaPtr[0];
    const int lane = threadIdx.x & 31;
    const int w = threadIdx.x >> 5;
    const int wm = w & 3, wn = w >> 2;
    const int gm_base = m0 + wm * 32 + (lane >> 2);
    const int gn_base = n0 + wn * 64 + (lane & 3) * 2;

#pragma unroll
    for (int mt = 0; mt < 2; ++mt) {
#pragma unroll
        for (int nt = 0; nt < 8; ++nt) {
            const int gi = gn_base + nt * 8;
            const int hh = gi >> 6, ww = gi & 63;
            const float cr = cIn[batch * MASKN + (hh >> 1) * 32 + (ww >> 1)];
            const float gb = gamma * (1.0f - cr);
#pragma unroll
            for (int half = 0; half < 2; ++half) {
                const int gm = gm_base + mt * 16 + half * 8;
                const size_t base = ((size_t)batch * CH + gm) * HWN + gi;
                float2 av = *reinterpret_cast<const float2*>(&aIn[base]);
                float2 o;
                o.x = av.x * cr + gb * acc[mt][nt][half * 2 + 0];
                o.y = av.y * cr + gb * acc[mt][nt][half * 2 + 1];
                *reinterpret_cast<float2*>(&out[base]) = o;
            }
        }
    }
}

// ---------------- launch ----------------
extern "C" void kernel_launch(void* const* d_in, const int* in_sizes, int n_in,
                              void* d_out, int out_size)
{
    const float* a     = (const float*)d_in[0];
    const float* b     = (const float*)d_in[1];
    const float* cmask = (const float*)d_in[2];
    const float* wq    = (const float*)d_in[3];
    const float* bq    = (const float*)d_in[4];
    const float* gq    = (const float*)d_in[5];
    const float* wk    = (const float*)d_in[6];
    const float* bk    = (const float*)d_in[7];
    const float* gk    = (const float*)d_in[8];
    const float* wv    = (const float*)d_in[9];
    const float* bv    = (const float*)d_in[10];
    const float* gv    = (const float*)d_in[11];
    const float* gamma = (const float*)d_in[12];
    float* out = (float*)d_out;

    k_ws<<<CH, 256>>>(wq, gq, 0);
    k_ws<<<CH, 256>>>(wk, gk, 1);
    k_ws<<<CH, 256>>>(wv, gv, 2);

    dim3 gqk(CH / BN, HWN / BM, 8);
    k_qkT<<<gqk, 256>>>(a, b, bq, bk);

    dim3 gv_(HWN / BN, CH / BM, BATCH);
    k_v<<<gv_, 256>>>(a, bv);

    dim3 gsim(HWN / 128, HWN / 128, BATCH);   // 32 x 32 x 4
    k_sim_mma<<<gsim, 256>>>();

    k_softmax<<<dim3(HWN, BATCH), 256>>>(cmask);

    dim3 gpv(HWN / 128, CH / 128, BATCH);     // 32 x 2 x 4
    k_pv_mma<<<gpv, 256>>>(a, cmask, gamma, out);
}

// round 8
// speedup vs baseline: 2.1035x; 1.1139x over previous
#include <cuda_runtime.h>
#include <cuda_bf16.h>
#include <math_constants.h>
#include <cstdint>

#define BATCH 4
#define CH    256
#define HWN   4096
#define MASKN 1024

// ---------------- scratch ----------------
__device__ __nv_bfloat16 g_wn_hi[3][CH * CH];
__device__ __nv_bfloat16 g_wn_lo[3][CH * CH];
__device__ __nv_bfloat16 g_qT_hi[(size_t)BATCH * HWN * CH];
__device__ __nv_bfloat16 g_qT_lo[(size_t)BATCH * HWN * CH];
__device__ __nv_bfloat16 g_kT_hi[(size_t)BATCH * HWN * CH];
__device__ __nv_bfloat16 g_kT_lo[(size_t)BATCH * HWN * CH];
__device__ __nv_bfloat16 g_v_hi[(size_t)BATCH * CH * HWN];
__device__ __nv_bfloat16 g_v_lo[(size_t)BATCH * CH * HWN];
__device__ float g_sim[(size_t)BATCH * HWN * HWN];
__device__ __nv_bfloat16 g_att_hi[(size_t)BATCH * HWN * HWN];
__device__ __nv_bfloat16 g_att_lo[(size_t)BATCH * HWN * HWN];

// aT/bT scratch aliased into g_att_hi (dead until k_softmax writes it;
// all aT/bT consumers run before k_softmax in the serial stream).
#define SPLIT_ELEMS ((size_t)BATCH * HWN * CH)   // 4,194,304 elems = 8 MiB
__device__ __forceinline__ __nv_bfloat16* xT_ptr(int which, int part) {
    // which: 0=a, 1=b ; part: 0=hi, 1=lo
    return g_att_hi + (size_t)(which * 2 + part) * SPLIT_ELEMS;
}

// ---------------- helpers ----------------
__device__ __forceinline__ uint32_t smem_u32(const void* p) {
    uint32_t a;
    asm("{ .reg .u64 t; cvta.to.shared.u64 t, %1; cvt.u32.u64 %0, t; }" : "=r"(a) : "l"(p));
    return a;
}
__device__ __forceinline__ void cp16(uint32_t dst, const void* src) {
    asm volatile("cp.async.cg.shared.global [%0], [%1], 16;" :: "r"(dst), "l"(src));
}
#define CP_COMMIT() asm volatile("cp.async.commit_group;")
#define CP_WAIT1()  asm volatile("cp.async.wait_group 1;")
#define CP_WAIT0()  asm volatile("cp.async.wait_group 0;")

__device__ __forceinline__ void ldsm_x4(uint32_t addr, uint32_t r[4]) {
    asm volatile("ldmatrix.sync.aligned.m8n8.x4.shared.b16 {%0,%1,%2,%3}, [%4];"
                 : "=r"(r[0]), "=r"(r[1]), "=r"(r[2]), "=r"(r[3]) : "r"(addr));
}
__device__ __forceinline__ void mma16816(float c[4], const uint32_t a[4], const uint32_t b[2]) {
    asm volatile("mma.sync.aligned.m16n8k16.row.col.f32.bf16.bf16.f32 "
                 "{%0,%1,%2,%3}, {%4,%5,%6,%7}, {%8,%9}, {%0,%1,%2,%3};"
                 : "+f"(c[0]), "+f"(c[1]), "+f"(c[2]), "+f"(c[3])
                 : "r"(a[0]), "r"(a[1]), "r"(a[2]), "r"(a[3]), "r"(b[0]), "r"(b[1]));
}

// tile layout: 128 rows x 32 bytes (16 bf16), swizzled so ldmatrix is conflict-free
__device__ __forceinline__ uint32_t swoff(int row, int seg) {
    return (uint32_t)row * 32 + ((seg ^ ((row >> 2) & 1)) << 4);
}

#define TILE16B 4096                     // 128 x 32B
// stage buffers: [stage][tile(Ah,Al,Bh,Bl)][4KB]  = 32KB
struct MmaSmem { char buf[2][4][TILE16B]; };

__device__ __forceinline__ void cp_tile16(uint32_t sdst, const __nv_bfloat16* g,
                                          size_t ld, int row0, int k0) {
    const int t = threadIdx.x;
    const int row = t >> 1;
    const int seg = t & 1;
    const char* src = reinterpret_cast<const char*>(g + (size_t)(row0 + row) * ld + k0 + seg * 8);
    cp16(sdst + swoff(row, seg), src);
}

__device__ __forceinline__ void load_stage16(uint32_t sb,
    const __nv_bfloat16* Ah, const __nv_bfloat16* Al, size_t lda, int m0,
    const __nv_bfloat16* Bh, const __nv_bfloat16* Bl, size_t ldb, int n0, int k0)
{
    cp_tile16(sb,               Ah, lda, m0, k0);
    cp_tile16(sb + TILE16B,     Al, lda, m0, k0);
    cp_tile16(sb + 2 * TILE16B, Bh, ldb, n0, k0);
    cp_tile16(sb + 3 * TILE16B, Bl, ldb, n0, k0);
}

// one k=16 slice: acc += Ah*Bh + Ah*Bl + Al*Bh   (warp tile 32x64)
__device__ __forceinline__ void compute_stage16(uint32_t sb, float acc[2][8][4],
                                                int lane, int wm, int wn)
{
    const uint32_t sAh = sb, sAl = sb + TILE16B, sBh = sb + 2 * TILE16B, sBl = sb + 3 * TILE16B;
    uint32_t ah[2][4], al[2][4];
    const int aseg = lane >> 4;
#pragma unroll
    for (int mt = 0; mt < 2; ++mt) {
        const int arow = wm * 32 + mt * 16 + (lane & 15);
        ldsm_x4(sAh + swoff(arow, aseg), ah[mt]);
        ldsm_x4(sAl + swoff(arow, aseg), al[mt]);
    }
    const int brow_in = ((lane >> 4) << 3) + (lane & 7);
    const int bseg = (lane >> 3) & 1;
#pragma unroll
    for (int ntp = 0; ntp < 4; ++ntp) {
        const int brow = wn * 64 + ntp * 16 + brow_in;
        uint32_t bh[4], bl[4];
        ldsm_x4(sBh + swoff(brow, bseg), bh);
        ldsm_x4(sBl + swoff(brow, bseg), bl);
#pragma unroll
        for (int mt = 0; mt < 2; ++mt) {
#pragma unroll
            for (int h = 0; h < 2; ++h) {
                const int nt = ntp * 2 + h;
                mma16816(acc[mt][nt], ah[mt], bh + h * 2);
                mma16816(acc[mt][nt], ah[mt], bl + h * 2);
                mma16816(acc[mt][nt], al[mt], bh + h * 2);
            }
        }
    }
}

// C[128x128] = A[m0..+128, :k] * B[n0..+128, :k]^T (both [row][k], 3-term hi/lo)
// 2-stage double buffer (R5-proven)
__device__ __forceinline__ void gemm_hilo(uint32_t sb0,
    const __nv_bfloat16* Ah, const __nv_bfloat16* Al, size_t lda, int m0,
    const __nv_bfloat16* Bh, const __nv_bfloat16* Bl, size_t ldb, int n0,
    int kTotal, float acc[2][8][4])
{
    const int lane = threadIdx.x & 31;
    const int w = threadIdx.x >> 5;
    const int wm = w & 3, wn = w >> 2;
    const int nk = kTotal / 16;

    load_stage16(sb0, Ah, Al, lda, m0, Bh, Bl, ldb, n0, 0);
    CP_COMMIT();
    for (int kc = 0; kc < nk; ++kc) {
        if (kc + 1 < nk) {
            load_stage16(sb0 + ((kc + 1) & 1) * (4 * TILE16B),
                         Ah, Al, lda, m0, Bh, Bl, ldb, n0, (kc + 1) * 16);
            CP_COMMIT();
            CP_WAIT1();
        } else {
            CP_WAIT0();
        }
        __syncthreads();
        compute_stage16(sb0 + (kc & 1) * (4 * TILE16B), acc, lane, wm, wn);
        __syncthreads();
    }
}

__device__ __forceinline__ void split_hilo(float v, __nv_bfloat16& h, __nv_bfloat16& l) {
    h = __float2bfloat16_rn(v);
    l = __float2bfloat16_rn(v - __bfloat162float(h));
}

// ---------------- kernel 0: weight standardization -> wn bf16 hi/lo ----------------
__global__ __launch_bounds__(256) void k_ws(const float* __restrict__ w,
                                            const float* __restrict__ gain, int which)
{
    const int o = blockIdx.x;
    const int t = threadIdx.x;
    const float v = w[o * CH + t];
    float s = v, ss = v * v;
#pragma unroll
    for (int off = 16; off; off >>= 1) {
        s  += __shfl_xor_sync(0xFFFFFFFFu, s,  off);
        ss += __shfl_xor_sync(0xFFFFFFFFu, ss, off);
    }
    __shared__ float sh_s[8], sh_ss[8], sh_scale, sh_msc;
    if ((t & 31) == 0) { sh_s[t >> 5] = s; sh_ss[t >> 5] = ss; }
    __syncthreads();
    if (t == 0) {
        float S = 0.f, SS = 0.f;
#pragma unroll
        for (int k = 0; k < 8; ++k) { S += sh_s[k]; SS += sh_ss[k]; }
        float mean = S * (1.0f / CH);
        float var  = (SS - (float)CH * mean * mean) * (1.0f / (CH - 1));
        float scale = rsqrtf(fmaxf(var * (float)CH, 1e-4f)) * gain[o];
        sh_scale = scale;
        sh_msc   = mean * scale;
    }
    __syncthreads();
    const float wn = v * sh_scale - sh_msc;
    __nv_bfloat16 h, l;
    split_hilo(wn, h, l);
    g_wn_hi[which][o * CH + t] = h;
    g_wn_lo[which][o * CH + t] = l;
}

// ---------------- kernel 1: transpose+split  x[b][c][hw] fp32 -> xT[b][hw][c] bf16 hi/lo ----------------
__global__ __launch_bounds__(256) void k_split(const float* __restrict__ x, int which)
{
    __shared__ float t[64][65];
    const int batch = blockIdx.z;
    const int hw0 = blockIdx.x * 64;
    const int c0  = blockIdx.y * 64;
    const float* __restrict__ src = x + (size_t)batch * CH * HWN;
    const int tid = threadIdx.x;

    const int lr = tid >> 6;        // 0..3
    const int lc = tid & 63;
#pragma unroll
    for (int i = 0; i < 16; ++i) {
        const int r = i * 4 + lr;   // c index
        t[r][lc] = src[(size_t)(c0 + r) * HWN + hw0 + lc];
    }
    __syncthreads();

    __nv_bfloat16* __restrict__ H = xT_ptr(which, 0) + (size_t)batch * HWN * CH;
    __nv_bfloat16* __restrict__ L = xT_ptr(which, 1) + (size_t)batch * HWN * CH;
    const int wr = tid >> 5;        // 0..7
    const int wc = (tid & 31) * 2;  // c pair
#pragma unroll
    for (int i = 0; i < 8; ++i) {
        const int r = i * 8 + wr;   // hw index
        float v0 = t[wc][r], v1 = t[wc + 1][r];
        __nv_bfloat16 h0, l0, h1, l1;
        split_hilo(v0, h0, l0);
        split_hilo(v1, h1, l1);
        const size_t o = (size_t)(hw0 + r) * CH + c0 + wc;
        *reinterpret_cast<__nv_bfloat162*>(&H[o]) = __nv_bfloat162(h0, h1);
        *reinterpret_cast<__nv_bfloat162*>(&L[o]) = __nv_bfloat162(l0, l1);
    }
}

// ---------------- kernel 2: qT/kT = xT @ wn^T (mma), out [hw][c] hi/lo ----------------
__global__ __launch_bounds__(256) void k_qk_mma(const float* __restrict__ bq,
                                                const float* __restrict__ bk)
{
    __shared__ __align__(1024) MmaSmem sm;
    const uint32_t sb0 = smem_u32(&sm);

    const int which = blockIdx.z >> 2;
    const int batch = blockIdx.z & 3;
    const size_t xoff = (size_t)batch * HWN * CH;
    const __nv_bfloat16* Xh = xT_ptr(which, 0) + xoff;
    const __nv_bfloat16* Xl = xT_ptr(which, 1) + xoff;
    const __nv_bfloat16* Wh = g_wn_hi[which];
    const __nv_bfloat16* Wl = g_wn_lo[which];
    const float* __restrict__ bias = which ? bk : bq;
    __nv_bfloat16* __restrict__ Hi = (which ? g_kT_hi : g_qT_hi) + xoff;
    __nv_bfloat16* __restrict__ Lo = (which ? g_kT_lo : g_qT_lo) + xoff;

    const int m0 = blockIdx.y * 128;   // hw
    const int n0 = blockIdx.x * 128;   // co

    float acc[2][8][4] = {};
    gemm_hilo(sb0, Xh, Xl, CH, m0, Wh, Wl, CH, n0, CH, acc);

    const int lane = threadIdx.x & 31;
    const int w = threadIdx.x >> 5;
    const int wm = w & 3, wn = w >> 2;
    const int gm_base = m0 + wm * 32 + (lane >> 2);
    const int gn_base = n0 + wn * 64 + (lane & 3) * 2;
#pragma unroll
    for (int mt = 0; mt < 2; ++mt) {
#pragma unroll
        for (int nt = 0; nt < 8; ++nt) {
            const int gn = gn_base + nt * 8;
            const float b0 = bias[gn], b1 = bias[gn + 1];
#pragma unroll
            for (int half = 0; half < 2; ++half) {
                const int gm = gm_base + mt * 16 + half * 8;
                float v0 = acc[mt][nt][half * 2 + 0] + b0;
                float v1 = acc[mt][nt][half * 2 + 1] + b1;
                __nv_bfloat16 h0, l0, h1, l1;
                split_hilo(v0, h0, l0);
                split_hilo(v1, h1, l1);
                const size_t o = (size_t)gm * CH + gn;
                *reinterpret_cast<__nv_bfloat162*>(&Hi[o]) = __nv_bfloat162(h0, h1);
                *reinterpret_cast<__nv_bfloat162*>(&Lo[o]) = __nv_bfloat162(l0, l1);
            }
        }
    }
}

// ---------------- kernel 3: v = wn @ aT^T (mma), out [c][hw] hi/lo ----------------
__global__ __launch_bounds__(256) void k_v_mma(const float* __restrict__ bv)
{
    __shared__ __align__(1024) MmaSmem sm;
    const uint32_t sb0 = smem_u32(&sm);

    const int batch = blockIdx.z;
    const size_t xoff = (size_t)batch * HWN * CH;
    const size_t voff = (size_t)batch * CH * HWN;

    const int m0 = blockIdx.y * 128;   // c
    const int n0 = blockIdx.x * 128;   // hw

    float acc[2][8][4] = {};
    gemm_hilo(sb0, g_wn_hi[2], g_wn_lo[2], CH, m0,
              xT_ptr(0, 0) + xoff, xT_ptr(0, 1) + xoff, CH, n0, CH, acc);

    const int lane = threadIdx.x & 31;
    const int w = threadIdx.x >> 5;
    const int wm = w & 3, wn = w >> 2;
    const int gm_base = m0 + wm * 32 + (lane >> 2);
    const int gn_base = n0 + wn * 64 + (lane & 3) * 2;
#pragma unroll
    for (int mt = 0; mt < 2; ++mt) {
#pragma unroll
        for (int nt = 0; nt < 8; ++nt) {
            const int gn = gn_base + nt * 8;
#pragma unroll
            for (int half = 0; half < 2; ++half) {
                const int gm = gm_base + mt * 16 + half * 8;
                const float bb = bv[gm];
                float v0 = acc[mt][nt][half * 2 + 0] + bb;
                float v1 = acc[mt][nt][half * 2 + 1] + bb;
                __nv_bfloat16 h0, l0, h1, l1;
                split_hilo(v0, h0, l0);
                split_hilo(v1, h1, l1);
                const size_t o = voff + (size_t)gm * HWN + gn;
                *reinterpret_cast<__nv_bfloat162*>(&g_v_hi[o]) = __nv_bfloat162(h0, h1);
                *reinterpret_cast<__nv_bfloat162*>(&g_v_lo[o]) = __nv_bfloat162(l0, l1);
            }
        }
    }
}

// ---------------- kernel 4: sim = qT @ kT^T (mma.sync) ----------------
__global__ __launch_bounds__(256) void k_sim_mma()
{
    __shared__ __align__(1024) MmaSmem sm;
    const uint32_t sb0 = smem_u32(&sm);

    const int batch = blockIdx.z;
    const int m0 = blockIdx.y * 128;
    const int n0 = blockIdx.x * 128;
    const size_t boff = (size_t)batch * HWN * CH;

    float acc[2][8][4] = {};
    gemm_hilo(sb0, g_qT_hi + boff, g_qT_lo + boff, CH, m0,
              g_kT_hi + boff, g_kT_lo + boff, CH, n0, CH, acc);

    float* __restrict__ S = g_sim + (size_t)batch * HWN * HWN;
    const int lane = threadIdx.x & 31;
    const int w = threadIdx.x >> 5;
    const int wm = w & 3, wn = w >> 2;
    const int gm_base = m0 + wm * 32 + (lane >> 2);
    const int gn_base = n0 + wn * 64 + (lane & 3) * 2;
#pragma unroll
    for (int mt = 0; mt < 2; ++mt) {
#pragma unroll
        for (int nt = 0; nt < 8; ++nt) {
            const int gm = gm_base + mt * 16;
            const int gn = gn_base + nt * 8;
            float2 p0 = {acc[mt][nt][0], acc[mt][nt][1]};
            float2 p1 = {acc[mt][nt][2], acc[mt][nt][3]};
            *reinterpret_cast<float2*>(&S[(size_t)gm * HWN + gn]) = p0;
            *reinterpret_cast<float2*>(&S[(size_t)(gm + 8) * HWN + gn]) = p1;
        }
    }
}

// ---------------- kernel 5: masked softmax -> att bf16 hi/lo ----------------
__global__ __launch_bounds__(256) void k_softmax(const float* __restrict__ cIn)
{
    const int i = blockIdx.x;
    const int batch = blockIdx.y;
    const float* __restrict__ row = g_sim + ((size_t)batch * HWN + i) * HWN;
    __nv_bfloat16* __restrict__ Hi = g_att_hi + ((size_t)batch * HWN + i) * HWN;
    __nv_bfloat16* __restrict__ Lo = g_att_lo + ((size_t)batch * HWN + i) * HWN;

    const int h = i >> 6, w = i & 63;
    const float m = cIn[batch * MASKN + (h >> 1) * 32 + (w >> 1)];

    const int tid = threadIdx.x;
    float x[16];
    float vmax = -CUDART_INF_F;
#pragma unroll
    for (int p = 0; p < 4; ++p) {
        float4 v = *reinterpret_cast<const float4*>(&row[(p * 256 + tid) * 4]);
        x[p * 4 + 0] = m * v.x; x[p * 4 + 1] = m * v.y;
        x[p * 4 + 2] = m * v.z; x[p * 4 + 3] = m * v.w;
#pragma unroll
        for (int q = 0; q < 4; ++q) vmax = fmaxf(vmax, x[p * 4 + q]);
    }

    __shared__ float redm[8], reds[8], sh_max, sh_sum;
#pragma unroll
    for (int off = 16; off; off >>= 1) vmax = fmaxf(vmax, __shfl_xor_sync(0xFFFFFFFFu, vmax, off));
    if ((tid & 31) == 0) redm[tid >> 5] = vmax;
    __syncthreads();
    if (tid == 0) {
        float v = redm[0];
#pragma unroll
        for (int k = 1; k < 8; ++k) v = fmaxf(v, redm[k]);
        sh_max = v;
    }
    __syncthreads();
    const float M = sh_max;

    float total = 0.f;
#pragma unroll
    for (int q = 0; q < 16; ++q) {
        float e = __expf(x[q] - M);
        x[q] = e;
        total += e;
    }
#pragma unroll
    for (int off = 16; off; off >>= 1) total += __shfl_xor_sync(0xFFFFFFFFu, total, off);
    if ((tid & 31) == 0) reds[tid >> 5] = total;
    __syncthreads();
    if (tid == 0) {
        float v = 0.f;
#pragma unroll
        for (int k = 0; k < 8; ++k) v += reds[k];
        sh_sum = v;
    }
    __syncthreads();
    const float inv = 1.0f / sh_sum;

#pragma unroll
    for (int p = 0; p < 4; ++p) {
        const int idx = (p * 256 + tid) * 4;
#pragma unroll
        for (int q = 0; q < 4; q += 2) {
            float v0 = x[p * 4 + q] * inv;
            float v1 = x[p * 4 + q + 1] * inv;
            __nv_bfloat16 h0, l0, h1, l1;
            split_hilo(v0, h0, l0);
            split_hilo(v1, h1, l1);
            *reinterpret_cast<__nv_bfloat162*>(&Hi[idx + q]) = __nv_bfloat162(h0, h1);
            *reinterpret_cast<__nv_bfloat162*>(&Lo[idx + q]) = __nv_bfloat162(l0, l1);
        }
    }
}

// ---------------- kernel 6: out = v @ att^T (mma.sync), fused blend ----------------
__global__ __launch_bounds__(256) void k_pv_mma(const float* __restrict__ aIn,
                                                const float* __restrict__ cIn,
                                                const float* __restrict__ gammaPtr,
                                                float* __restrict__ out)
{
    __shared__ __align__(1024) MmaSmem sm;
    const uint32_t sb0 = smem_u32(&sm);

    const int batch = blockIdx.z;
    const int m0 = blockIdx.y * 128;   // channel
    const int n0 = blockIdx.x * 128;   // position i
    const size_t voff = (size_t)batch * CH * HWN;
    const size_t aoff = (size_t)batch * HWN * HWN;

    float acc[2][8][4] = {};
    gemm_hilo(sb0, g_v_hi + voff, g_v_lo + voff, HWN, m0,
              g_att_hi + aoff, g_att_lo + aoff, HWN, n0, HWN, acc);

    const float gamma = gammaPtr[0];
    const int lane = threadIdx.x & 31;
    const int w = threadIdx.x >> 5;
    const int wm = w & 3, wn = w >> 2;
    const int gm_base = m0 + wm * 32 + (lane >> 2);
    const int gn_base = n0 + wn * 64 + (lane & 3) * 2;

#pragma unroll
    for (int mt = 0; mt < 2; ++mt) {
#pragma unroll
        for (int nt = 0; nt < 8; ++nt) {
            const int gi = gn_base + nt * 8;
            const int hh = gi >> 6, ww = gi & 63;
            const float cr = cIn[batch * MASKN + (hh >> 1) * 32 + (ww >> 1)];
            const float gb = gamma * (1.0f - cr);
#pragma unroll
            for (int half = 0; half < 2; ++half) {
                const int gm = gm_base + mt * 16 + half * 8;
                const size_t base = ((size_t)batch * CH + gm) * HWN + gi;
                float2 av = *reinterpret_cast<const float2*>(&aIn[base]);
                float2 o;
                o.x = av.x * cr + gb * acc[mt][nt][half * 2 + 0];
                o.y = av.y * cr + gb * acc[mt][nt][half * 2 + 1];
                *reinterpret_cast<float2*>(&out[base]) = o;
            }
        }
    }
}

// ---------------- launch ----------------
extern "C" void kernel_launch(void* const* d_in, const int* in_sizes, int n_in,
                              void* d_out, int out_size)
{
    const float* a     = (const float*)d_in[0];
    const float* b     = (const float*)d_in[1];
    const float* cmask = (const float*)d_in[2];
    const float* wq    = (const float*)d_in[3];
    const float* bq    = (const float*)d_in[4];
    const float* gq    = (const float*)d_in[5];
    const float* wk    = (const float*)d_in[6];
    const float* bk    = (const float*)d_in[7];
    const float* gk    = (const float*)d_in[8];
    const float* wv    = (const float*)d_in[9];
    const float* bv    = (const float*)d_in[10];
    const float* gv    = (const float*)d_in[11];
    const float* gamma = (const float*)d_in[12];
    float* out = (float*)d_out;

    k_ws<<<CH, 256>>>(wq, gq, 0);
    k_ws<<<CH, 256>>>(wk, gk, 1);
    k_ws<<<CH, 256>>>(wv, gv, 2);

    dim3 gsp(HWN / 64, CH / 64, BATCH);       // 64 x 4 x 4
    k_split<<<gsp, 256>>>(a, 0);
    k_split<<<gsp, 256>>>(b, 1);

    dim3 gqk(CH / 128, HWN / 128, 8);         // 2 x 32 x 8
    k_qk_mma<<<gqk, 256>>>(bq, bk);

    dim3 gvv(HWN / 128, CH / 128, BATCH);     // 32 x 2 x 4
    k_v_mma<<<gvv, 256>>>(bv);

    dim3 gsim(HWN / 128, HWN / 128, BATCH);   // 32 x 32 x 4
    k_sim_mma<<<gsim, 256>>>();

    k_softmax<<<dim3(HWN, BATCH), 256>>>(cmask);

    dim3 gpv(HWN / 128, CH / 128, BATCH);     // 32 x 2 x 4
    k_pv_mma<<<gpv, 256>>>(a, cmask, gamma, out);
}

// round 9
// speedup vs baseline: 2.3318x; 1.1085x over previous
#include <cuda_runtime.h>
#include <cuda_bf16.h>
#include <math_constants.h>
#include <cstdint>

#define BATCH 4
#define CH    256
#define HWN   4096
#define MASKN 1024

// ---------------- scratch ----------------
__device__ __nv_bfloat16 g_wn_hi[3][CH * CH];
__device__ __nv_bfloat16 g_wn_lo[3][CH * CH];
__device__ __nv_bfloat16 g_qT_hi[(size_t)BATCH * HWN * CH];
__device__ __nv_bfloat16 g_qT_lo[(size_t)BATCH * HWN * CH];
__device__ __nv_bfloat16 g_kT_hi[(size_t)BATCH * HWN * CH];
__device__ __nv_bfloat16 g_kT_lo[(size_t)BATCH * HWN * CH];
__device__ __nv_bfloat16 g_v_hi[(size_t)BATCH * CH * HWN];
__device__ __nv_bfloat16 g_v_lo[(size_t)BATCH * CH * HWN];
__device__ float g_sim[(size_t)BATCH * HWN * HWN];
__device__ __nv_bfloat16 g_att_hi[(size_t)BATCH * HWN * HWN];
__device__ __nv_bfloat16 g_att_lo[(size_t)BATCH * HWN * HWN];

// aT/bT scratch aliased into g_att_hi (dead until k_softmax writes it;
// all aT/bT consumers run before k_softmax in the serial stream).
#define SPLIT_ELEMS ((size_t)BATCH * HWN * CH)   // 8 MiB each
__device__ __forceinline__ __nv_bfloat16* xT_ptr(int which, int part) {
    return g_att_hi + (size_t)(which * 2 + part) * SPLIT_ELEMS;
}

// ---------------- helpers ----------------
__device__ __forceinline__ uint32_t smem_u32(const void* p) {
    uint32_t a;
    asm("{ .reg .u64 t; cvta.to.shared.u64 t, %1; cvt.u32.u64 %0, t; }" : "=r"(a) : "l"(p));
    return a;
}
__device__ __forceinline__ void cp16(uint32_t dst, const void* src) {
    asm volatile("cp.async.cg.shared.global [%0], [%1], 16;" :: "r"(dst), "l"(src));
}
#define CP_COMMIT() asm volatile("cp.async.commit_group;")
#define CP_WAIT1()  asm volatile("cp.async.wait_group 1;")
#define CP_WAIT0()  asm volatile("cp.async.wait_group 0;")

__device__ __forceinline__ void ldsm_x4(uint32_t addr, uint32_t r[4]) {
    asm volatile("ldmatrix.sync.aligned.m8n8.x4.shared.b16 {%0,%1,%2,%3}, [%4];"
                 : "=r"(r[0]), "=r"(r[1]), "=r"(r[2]), "=r"(r[3]) : "r"(addr));
}
__device__ __forceinline__ void mma16816(float c[4], const uint32_t a[4], const uint32_t b[2]) {
    asm volatile("mma.sync.aligned.m16n8k16.row.col.f32.bf16.bf16.f32 "
                 "{%0,%1,%2,%3}, {%4,%5,%6,%7}, {%8,%9}, {%0,%1,%2,%3};"
                 : "+f"(c[0]), "+f"(c[1]), "+f"(c[2]), "+f"(c[3])
                 : "r"(a[0]), "r"(a[1]), "r"(a[2]), "r"(a[3]), "r"(b[0]), "r"(b[1]));
}

// tile layout: 128 rows x 32 bytes (16 bf16), swizzled so ldmatrix is conflict-free
__device__ __forceinline__ uint32_t swoff(int row, int seg) {
    return (uint32_t)row * 32 + ((seg ^ ((row >> 2) & 1)) << 4);
}

#define TILE16B 4096                     // 128 x 32B
#define STAGEB  (4 * TILE16B)            // 16KB per stage (Ah,Al,Bh,Bl)
// 3 stages = 48KB exactly (static smem ceiling)
struct MmaSmem { char buf[3][4][TILE16B]; };

__device__ __forceinline__ void cp_tile16(uint32_t sdst, const __nv_bfloat16* g,
                                          size_t ld, int row0, int k0) {
    const int t = threadIdx.x;
    const int row = t >> 1;
    const int seg = t & 1;
    const char* src = reinterpret_cast<const char*>(g + (size_t)(row0 + row) * ld + k0 + seg * 8);
    cp16(sdst + swoff(row, seg), src);
}

__device__ __forceinline__ void load_stage16(uint32_t sb,
    const __nv_bfloat16* Ah, const __nv_bfloat16* Al, size_t lda, int m0,
    const __nv_bfloat16* Bh, const __nv_bfloat16* Bl, size_t ldb, int n0, int k0)
{
    cp_tile16(sb,               Ah, lda, m0, k0);
    cp_tile16(sb + TILE16B,     Al, lda, m0, k0);
    cp_tile16(sb + 2 * TILE16B, Bh, ldb, n0, k0);
    cp_tile16(sb + 3 * TILE16B, Bl, ldb, n0, k0);
}

// one k=16 slice: acc += Ah*Bh + Ah*Bl + Al*Bh   (warp tile 32x64)
__device__ __forceinline__ void compute_stage16(uint32_t sb, float acc[2][8][4],
                                                int lane, int wm, int wn)
{
    const uint32_t sAh = sb, sAl = sb + TILE16B, sBh = sb + 2 * TILE16B, sBl = sb + 3 * TILE16B;
    uint32_t ah[2][4], al[2][4];
    const int aseg = lane >> 4;
#pragma unroll
    for (int mt = 0; mt < 2; ++mt) {
        const int arow = wm * 32 + mt * 16 + (lane & 15);
        ldsm_x4(sAh + swoff(arow, aseg), ah[mt]);
        ldsm_x4(sAl + swoff(arow, aseg), al[mt]);
    }
    const int brow_in = ((lane >> 4) << 3) + (lane & 7);
    const int bseg = (lane >> 3) & 1;
#pragma unroll
    for (int ntp = 0; ntp < 4; ++ntp) {
        const int brow = wn * 64 + ntp * 16 + brow_in;
        uint32_t bh[4], bl[4];
        ldsm_x4(sBh + swoff(brow, bseg), bh);
        ldsm_x4(sBl + swoff(brow, bseg), bl);
#pragma unroll
        for (int mt = 0; mt < 2; ++mt) {
#pragma unroll
            for (int h = 0; h < 2; ++h) {
                const int nt = ntp * 2 + h;
                mma16816(acc[mt][nt], ah[mt], bh + h * 2);
                mma16816(acc[mt][nt], ah[mt], bl + h * 2);
                mma16816(acc[mt][nt], al[mt], bh + h * 2);
            }
        }
    }
}

// one pipeline step: wait for stage s, prefetch stage s+2 into pbase, compute stage s
__device__ __forceinline__ void pipe_step(int s, int nk, uint32_t cbase, uint32_t pbase,
    const __nv_bfloat16* Ah, const __nv_bfloat16* Al, size_t lda, int m0,
    const __nv_bfloat16* Bh, const __nv_bfloat16* Bl, size_t ldb, int n0,
    float acc[2][8][4], int lane, int wm, int wn)
{
    if (s >= nk) return;
    if (s + 1 < nk) CP_WAIT1(); else CP_WAIT0();
    __syncthreads();   // stage-s data visible AND all warps done computing stage s-1
    if (s + 2 < nk) {
        load_stage16(pbase, Ah, Al, lda, m0, Bh, Bl, ldb, n0, (s + 2) * 16);
        CP_COMMIT();
    }
    compute_stage16(cbase, acc, lane, wm, wn);
}

// C[128x128] = A[m0..+128, :k] * B[n0..+128, :k]^T (both [row][k], 3-term hi/lo)
// 3-stage pipeline, compile-time buffer indices, one barrier per chunk
__device__ __forceinline__ void gemm_hilo(uint32_t sb0,
    const __nv_bfloat16* Ah, const __nv_bfloat16* Al, size_t lda, int m0,
    const __nv_bfloat16* Bh, const __nv_bfloat16* Bl, size_t ldb, int n0,
    int kTotal, float acc[2][8][4])
{
    const int lane = threadIdx.x & 31;
    const int w = threadIdx.x >> 5;
    const int wm = w & 3, wn = w >> 2;
    const int nk = kTotal / 16;
    const uint32_t b0 = sb0, b1 = sb0 + STAGEB, b2 = sb0 + 2 * STAGEB;

    load_stage16(b0, Ah, Al, lda, m0, Bh, Bl, ldb, n0, 0);
    CP_COMMIT();
    if (nk > 1) {
        load_stage16(b1, Ah, Al, lda, m0, Bh, Bl, ldb, n0, 16);
        CP_COMMIT();
    }
    for (int s0 = 0; s0 < nk; s0 += 3) {
        pipe_step(s0 + 0, nk, b0, b2, Ah, Al, lda, m0, Bh, Bl, ldb, n0, acc, lane, wm, wn);
        pipe_step(s0 + 1, nk, b1, b0, Ah, Al, lda, m0, Bh, Bl, ldb, n0, acc, lane, wm, wn);
        pipe_step(s0 + 2, nk, b2, b1, Ah, Al, lda, m0, Bh, Bl, ldb, n0, acc, lane, wm, wn);
    }
}

__device__ __forceinline__ void split_hilo(float v, __nv_bfloat16& h, __nv_bfloat16& l) {
    h = __float2bfloat16_rn(v);
    l = __float2bfloat16_rn(v - __bfloat162float(h));
}

// ---------------- kernel 0: weight standardization -> wn bf16 hi/lo ----------------
__global__ __launch_bounds__(256) void k_ws(const float* __restrict__ w,
                                            const float* __restrict__ gain, int which)
{
    const int o = blockIdx.x;
    const int t = threadIdx.x;
    const float v = w[o * CH + t];
    float s = v, ss = v * v;
#pragma unroll
    for (int off = 16; off; off >>= 1) {
        s  += __shfl_xor_sync(0xFFFFFFFFu, s,  off);
        ss += __shfl_xor_sync(0xFFFFFFFFu, ss, off);
    }
    __shared__ float sh_s[8], sh_ss[8], sh_scale, sh_msc;
    if ((t & 31) == 0) { sh_s[t >> 5] = s; sh_ss[t >> 5] = ss; }
    __syncthreads();
    if (t == 0) {
        float S = 0.f, SS = 0.f;
#pragma unroll
        for (int k = 0; k < 8; ++k) { S += sh_s[k]; SS += sh_ss[k]; }
        float mean = S * (1.0f / CH);
        float var  = (SS - (float)CH * mean * mean) * (1.0f / (CH - 1));
        float scale = rsqrtf(fmaxf(var * (float)CH, 1e-4f)) * gain[o];
        sh_scale = scale;
        sh_msc   = mean * scale;
    }
    __syncthreads();
    const float wn = v * sh_scale - sh_msc;
    __nv_bfloat16 h, l;
    split_hilo(wn, h, l);
    g_wn_hi[which][o * CH + t] = h;
    g_wn_lo[which][o * CH + t] = l;
}

// ---------------- kernel 1: transpose+split  x[b][c][hw] fp32 -> xT[b][hw][c] bf16 hi/lo ----------------
__global__ __launch_bounds__(256) void k_split(const float* __restrict__ x, int which)
{
    __shared__ float t[64][65];
    const int batch = blockIdx.z;
    const int hw0 = blockIdx.x * 64;
    const int c0  = blockIdx.y * 64;
    const float* __restrict__ src = x + (size_t)batch * CH * HWN;
    const int tid = threadIdx.x;

    const int lr = tid >> 6;
    const int lc = tid & 63;
#pragma unroll
    for (int i = 0; i < 16; ++i) {
        const int r = i * 4 + lr;
        t[r][lc] = src[(size_t)(c0 + r) * HWN + hw0 + lc];
    }
    __syncthreads();

    __nv_bfloat16* __restrict__ H = xT_ptr(which, 0) + (size_t)batch * HWN * CH;
    __nv_bfloat16* __restrict__ L = xT_ptr(which, 1) + (size_t)batch * HWN * CH;
    const int wr = tid >> 5;
    const int wc = (tid & 31) * 2;
#pragma unroll
    for (int i = 0; i < 8; ++i) {
        const int r = i * 8 + wr;
        float v0 = t[wc][r], v1 = t[wc + 1][r];
        __nv_bfloat16 h0, l0, h1, l1;
        split_hilo(v0, h0, l0);
        split_hilo(v1, h1, l1);
        const size_t o = (size_t)(hw0 + r) * CH + c0 + wc;
        *reinterpret_cast<__nv_bfloat162*>(&H[o]) = __nv_bfloat162(h0, h1);
        *reinterpret_cast<__nv_bfloat162*>(&L[o]) = __nv_bfloat162(l0, l1);
    }
}

// ---------------- kernel 2: qT/kT = xT @ wn^T (mma), out [hw][c] hi/lo ----------------
__global__ __launch_bounds__(256) void k_qk_mma(const float* __restrict__ bq,
                                                const float* __restrict__ bk)
{
    __shared__ __align__(1024) MmaSmem sm;
    const uint32_t sb0 = smem_u32(&sm);

    const int which = blockIdx.z >> 2;
    const int batch = blockIdx.z & 3;
    const size_t xoff = (size_t)batch * HWN * CH;
    const __nv_bfloat16* Xh = xT_ptr(which, 0) + xoff;
    const __nv_bfloat16* Xl = xT_ptr(which, 1) + xoff;
    const __nv_bfloat16* Wh = g_wn_hi[which];
    const __nv_bfloat16* Wl = g_wn_lo[which];
    const float* __restrict__ bias = which ? bk : bq;
    __nv_bfloat16* __restrict__ Hi = (which ? g_kT_hi : g_qT_hi) + xoff;
    __nv_bfloat16* __restrict__ Lo = (which ? g_kT_lo : g_qT_lo) + xoff;

    const int m0 = blockIdx.y * 128;   // hw
    const int n0 = blockIdx.x * 128;   // co

    float acc[2][8][4] = {};
    gemm_hilo(sb0, Xh, Xl, CH, m0, Wh, Wl, CH, n0, CH, acc);

    const int lane = threadIdx.x & 31;
    const int w = threadIdx.x >> 5;
    const int wm = w & 3, wn = w >> 2;
    const int gm_base = m0 + wm * 32 + (lane >> 2);
    const int gn_base = n0 + wn * 64 + (lane & 3) * 2;
#pragma unroll
    for (int mt = 0; mt < 2; ++mt) {
#pragma unroll
        for (int nt = 0; nt < 8; ++nt) {
            const int gn = gn_base + nt * 8;
            const float b0 = bias[gn], b1 = bias[gn + 1];
#pragma unroll
            for (int half = 0; half < 2; ++half) {
                const int gm = gm_base + mt * 16 + half * 8;
                float v0 = acc[mt][nt][half * 2 + 0] + b0;
                float v1 = acc[mt][nt][half * 2 + 1] + b1;
                __nv_bfloat16 h0, l0, h1, l1;
                split_hilo(v0, h0, l0);
                split_hilo(v1, h1, l1);
                const size_t o = (size_t)gm * CH + gn;
                *reinterpret_cast<__nv_bfloat162*>(&Hi[o]) = __nv_bfloat162(h0, h1);
                *reinterpret_cast<__nv_bfloat162*>(&Lo[o]) = __nv_bfloat162(l0, l1);
            }
        }
    }
}

// ---------------- kernel 3: v = wn @ aT^T (mma), out [c][hw] hi/lo ----------------
__global__ __launch_bounds__(256) void k_v_mma(const float* __restrict__ bv)
{
    __shared__ __align__(1024) MmaSmem sm;
    const uint32_t sb0 = smem_u32(&sm);

    const int batch = blockIdx.z;
    const size_t xoff = (size_t)batch * HWN * CH;
    const size_t voff = (size_t)batch * CH * HWN;

    const int m0 = blockIdx.y * 128;   // c
    const int n0 = blockIdx.x * 128;   // hw

    float acc[2][8][4] = {};
    gemm_hilo(sb0, g_wn_hi[2], g_wn_lo[2], CH, m0,
              xT_ptr(0, 0) + xoff, xT_ptr(0, 1) + xoff, CH, n0, CH, acc);

    const int lane = threadIdx.x & 31;
    const int w = threadIdx.x >> 5;
    const int wm = w & 3, wn = w >> 2;
    const int gm_base = m0 + wm * 32 + (lane >> 2);
    const int gn_base = n0 + wn * 64 + (lane & 3) * 2;
#pragma unroll
    for (int mt = 0; mt < 2; ++mt) {
#pragma unroll
        for (int nt = 0; nt < 8; ++nt) {
            const int gn = gn_base + nt * 8;
#pragma unroll
            for (int half = 0; half < 2; ++half) {
                const int gm = gm_base + mt * 16 + half * 8;
                const float bb = bv[gm];
                float v0 = acc[mt][nt][half * 2 + 0] + bb;
                float v1 = acc[mt][nt][half * 2 + 1] + bb;
                __nv_bfloat16 h0, l0, h1, l1;
                split_hilo(v0, h0, l0);
                split_hilo(v1, h1, l1);
                const size_t o = voff + (size_t)gm * HWN + gn;
                *reinterpret_cast<__nv_bfloat162*>(&g_v_hi[o]) = __nv_bfloat162(h0, h1);
                *reinterpret_cast<__nv_bfloat162*>(&g_v_lo[o]) = __nv_bfloat162(l0, l1);
            }
        }
    }
}

// ---------------- kernel 4: sim = qT @ kT^T (mma.sync) ----------------
__global__ __launch_bounds__(256) void k_sim_mma()
{
    __shared__ __align__(1024) MmaSmem sm;
    const uint32_t sb0 = smem_u32(&sm);

    const int batch = blockIdx.z;
    const int m0 = blockIdx.y * 128;
    const int n0 = blockIdx.x * 128;
    const size_t boff = (size_t)batch * HWN * CH;

    float acc[2][8][4] = {};
    gemm_hilo(sb0, g_qT_hi + boff, g_qT_lo + boff, CH, m0,
              g_kT_hi + boff, g_kT_lo + boff, CH, n0, CH, acc);

    float* __restrict__ S = g_sim + (size_t)batch * HWN * HWN;
    const int lane = threadIdx.x & 31;
    const int w = threadIdx.x >> 5;
    const int wm = w & 3, wn = w >> 2;
    const int gm_base = m0 + wm * 32 + (lane >> 2);
    const int gn_base = n0 + wn * 64 + (lane & 3) * 2;
#pragma unroll
    for (int mt = 0; mt < 2; ++mt) {
#pragma unroll
        for (int nt = 0; nt < 8; ++nt) {
            const int gm = gm_base + mt * 16;
            const int gn = gn_base + nt * 8;
            float2 p0 = {acc[mt][nt][0], acc[mt][nt][1]};
            float2 p1 = {acc[mt][nt][2], acc[mt][nt][3]};
            *reinterpret_cast<float2*>(&S[(size_t)gm * HWN + gn]) = p0;
            *reinterpret_cast<float2*>(&S[(size_t)(gm + 8) * HWN + gn]) = p1;
        }
    }
}

// ---------------- kernel 5: masked softmax -> att bf16 hi/lo ----------------
__global__ __launch_bounds__(256) void k_softmax(const float* __restrict__ cIn)
{
    const int i = blockIdx.x;
    const int batch = blockIdx.y;
    const float* __restrict__ row = g_sim + ((size_t)batch * HWN + i) * HWN;
    __nv_bfloat16* __restrict__ Hi = g_att_hi + ((size_t)batch * HWN + i) * HWN;
    __nv_bfloat16* __restrict__ Lo = g_att_lo + ((size_t)batch * HWN + i) * HWN;

    const int h = i >> 6, w = i & 63;
    const float m = cIn[batch * MASKN + (h >> 1) * 32 + (w >> 1)];

    const int tid = threadIdx.x;
    float x[16];
    float vmax = -CUDART_INF_F;
#pragma unroll
    for (int p = 0; p < 4; ++p) {
        float4 v = *reinterpret_cast<const float4*>(&row[(p * 256 + tid) * 4]);
        x[p * 4 + 0] = m * v.x; x[p * 4 + 1] = m * v.y;
        x[p * 4 + 2] = m * v.z; x[p * 4 + 3] = m * v.w;
#pragma unroll
        for (int q = 0; q < 4; ++q) vmax = fmaxf(vmax, x[p * 4 + q]);
    }

    __shared__ float redm[8], reds[8], sh_max, sh_sum;
#pragma unroll
    for (int off = 16; off; off >>= 1) vmax = fmaxf(vmax, __shfl_xor_sync(0xFFFFFFFFu, vmax, off));
    if ((tid & 31) == 0) redm[tid >> 5] = vmax;
    __syncthreads();
    if (tid == 0) {
        float v = redm[0];
#pragma unroll
        for (int k = 1; k < 8; ++k) v = fmaxf(v, redm[k]);
        sh_max = v;
    }
    __syncthreads();
    const float M = sh_max;

    float total = 0.f;
#pragma unroll
    for (int q = 0; q < 16; ++q) {
        float e = __expf(x[q] - M);
        x[q] = e;
        total += e;
    }
#pragma unroll
    for (int off = 16; off; off >>= 1) total += __shfl_xor_sync(0xFFFFFFFFu, total, off);
    if ((tid & 31) == 0) reds[tid >> 5] = total;
    __syncthreads();
    if (tid == 0) {
        float v = 0.f;
#pragma unroll
        for (int k = 0; k < 8; ++k) v += reds[k];
        sh_sum = v;
    }
    __syncthreads();
    const float inv = 1.0f / sh_sum;

#pragma unroll
    for (int p = 0; p < 4; ++p) {
        const int idx = (p * 256 + tid) * 4;
#pragma unroll
        for (int q = 0; q < 4; q += 2) {
            float v0 = x[p * 4 + q] * inv;
            float v1 = x[p * 4 + q + 1] * inv;
            __nv_bfloat16 h0, l0, h1, l1;
            split_hilo(v0, h0, l0);
            split_hilo(v1, h1, l1);
            *reinterpret_cast<__nv_bfloat162*>(&Hi[idx + q]) = __nv_bfloat162(h0, h1);
            *reinterpret_cast<__nv_bfloat162*>(&Lo[idx + q]) = __nv_bfloat162(l0, l1);
        }
    }
}

// ---------------- kernel 6: out = v @ att^T (mma.sync), fused blend ----------------
__global__ __launch_bounds__(256) void k_pv_mma(const float* __restrict__ aIn,
                                                const float* __restrict__ cIn,
                                                const float* __restrict__ gammaPtr,
                                                float* __restrict__ out)
{
    __shared__ __align__(1024) MmaSmem sm;
    const uint32_t sb0 = smem_u32(&sm);

    const int batch = blockIdx.z;
    const int m0 = blockIdx.y * 128;   // channel
    const int n0 = blockIdx.x * 128;   // position i
    const size_t voff = (size_t)batch * CH * HWN;
    const size_t aoff = (size_t)batch * HWN * HWN;

    float acc[2][8][4] = {};
    gemm_hilo(sb0, g_v_hi + voff, g_v_lo + voff, HWN, m0,
              g_att_hi + aoff, g_att_lo + aoff, HWN, n0, HWN, acc);

    const float gamma = gammaPtr[0];
    const int lane = threadIdx.x & 31;
    const int w = threadIdx.x >> 5;
    const int wm = w & 3, wn = w >> 2;
    const int gm_base = m0 + wm * 32 + (lane >> 2);
    const int gn_base = n0 + wn * 64 + (lane & 3) * 2;

#pragma unroll
    for (int mt = 0; mt < 2; ++mt) {
#pragma unroll
        for (int nt = 0; nt < 8; ++nt) {
            const int gi = gn_base + nt * 8;
            const int hh = gi >> 6, ww = gi & 63;
            const float cr = cIn[batch * MASKN + (hh >> 1) * 32 + (ww >> 1)];
            const float gb = gamma * (1.0f - cr);
#pragma unroll
            for (int half = 0; half < 2; ++half) {
                const int gm = gm_base + mt * 16 + half * 8;
                const size_t base = ((size_t)batch * CH + gm) * HWN + gi;
                float2 av = *reinterpret_cast<const float2*>(&aIn[base]);
                float2 o;
                o.x = av.x * cr + gb * acc[mt][nt][half * 2 + 0];
                o.y = av.y * cr + gb * acc[mt][nt][half * 2 + 1];
                *reinterpret_cast<float2*>(&out[base]) = o;
            }
        }
    }
}

// ---------------- launch ----------------
extern "C" void kernel_launch(void* const* d_in, const int* in_sizes, int n_in,
                              void* d_out, int out_size)
{
    const float* a     = (const float*)d_in[0];
    const float* b     = (const float*)d_in[1];
    const float* cmask = (const float*)d_in[2];
    const float* wq    = (const float*)d_in[3];
    const float* bq    = (const float*)d_in[4];
    const float* gq    = (const float*)d_in[5];
    const float* wk    = (const float*)d_in[6];
    const float* bk    = (const float*)d_in[7];
    const float* gk    = (const float*)d_in[8];
    const float* wv    = (const float*)d_in[9];
    const float* bv    = (const float*)d_in[10];
    const float* gv    = (const float*)d_in[11];
    const float* gamma = (const float*)d_in[12];
    float* out = (float*)d_out;

    k_ws<<<CH, 256>>>(wq, gq, 0);
    k_ws<<<CH, 256>>>(wk, gk, 1);
    k_ws<<<CH, 256>>>(wv, gv, 2);

    dim3 gsp(HWN / 64, CH / 64, BATCH);
    k_split<<<gsp, 256>>>(a, 0);
    k_split<<<gsp, 256>>>(b, 1);

    dim3 gqk(CH / 128, HWN / 128, 8);
    k_qk_mma<<<gqk, 256>>>(bq, bk);

    dim3 gvv(HWN / 128, CH / 128, BATCH);
    k_v_mma<<<gvv, 256>>>(bv);

    dim3 gsim(HWN / 128, HWN / 128, BATCH);
    k_sim_mma<<<gsim, 256>>>();

    k_softmax<<<dim3(HWN, BATCH), 256>>>(cmask);

    dim3 gpv(HWN / 128, CH / 128, BATCH);
    k_pv_mma<<<gpv, 256>>>(a, cmask, gamma, out);
}

// round 10
// speedup vs baseline: 2.3521x; 1.0087x over previous
#include <cuda_runtime.h>
#include <cuda_bf16.h>
#include <math_constants.h>
#include <cstdint>

#define BATCH 4
#define CH    256
#define HWN   4096
#define MASKN 1024

// ---------------- scratch ----------------
__device__ __nv_bfloat16 g_wn_hi[3][CH * CH];
__device__ __nv_bfloat16 g_wn_lo[3][CH * CH];
__device__ __nv_bfloat16 g_qT_hi[(size_t)BATCH * HWN * CH];
__device__ __nv_bfloat16 g_qT_lo[(size_t)BATCH * HWN * CH];
__device__ __nv_bfloat16 g_kT_hi[(size_t)BATCH * HWN * CH];
__device__ __nv_bfloat16 g_kT_lo[(size_t)BATCH * HWN * CH];
__device__ __nv_bfloat16 g_v_hi[(size_t)BATCH * CH * HWN];
__device__ __nv_bfloat16 g_v_lo[(size_t)BATCH * CH * HWN];
__device__ float g_sim[(size_t)BATCH * HWN * HWN];
__device__ __nv_bfloat16 g_att_hi[(size_t)BATCH * HWN * HWN];
__device__ __nv_bfloat16 g_att_lo[(size_t)BATCH * HWN * HWN];

// aT/bT scratch aliased into g_att_hi (dead until k_softmax writes it;
// all aT/bT consumers run before k_softmax in the serial stream).
#define SPLIT_ELEMS ((size_t)BATCH * HWN * CH)   // 8 MiB each
__device__ __forceinline__ __nv_bfloat16* xT_ptr(int which, int part) {
    return g_att_hi + (size_t)(which * 2 + part) * SPLIT_ELEMS;
}

// ---------------- helpers ----------------
__device__ __forceinline__ uint32_t smem_u32(const void* p) {
    uint32_t a;
    asm("{ .reg .u64 t; cvta.to.shared.u64 t, %1; cvt.u32.u64 %0, t; }" : "=r"(a) : "l"(p));
    return a;
}
__device__ __forceinline__ void cp16(uint32_t dst, const void* src) {
    asm volatile("cp.async.cg.shared.global [%0], [%1], 16;" :: "r"(dst), "l"(src));
}
#define CP_COMMIT() asm volatile("cp.async.commit_group;")
#define CP_WAIT1()  asm volatile("cp.async.wait_group 1;")
#define CP_WAIT0()  asm volatile("cp.async.wait_group 0;")

__device__ __forceinline__ void ldsm_x4(uint32_t addr, uint32_t r[4]) {
    asm volatile("ldmatrix.sync.aligned.m8n8.x4.shared.b16 {%0,%1,%2,%3}, [%4];"
                 : "=r"(r[0]), "=r"(r[1]), "=r"(r[2]), "=r"(r[3]) : "r"(addr));
}
__device__ __forceinline__ void mma16816(float c[4], const uint32_t a[4], const uint32_t b[2]) {
    asm volatile("mma.sync.aligned.m16n8k16.row.col.f32.bf16.bf16.f32 "
                 "{%0,%1,%2,%3}, {%4,%5,%6,%7}, {%8,%9}, {%0,%1,%2,%3};"
                 : "+f"(c[0]), "+f"(c[1]), "+f"(c[2]), "+f"(c[3])
                 : "r"(a[0]), "r"(a[1]), "r"(a[2]), "r"(a[3]), "r"(b[0]), "r"(b[1]));
}

// tile layout: 128 rows x 32 bytes (16 bf16), swizzled so ldmatrix is conflict-free
__device__ __forceinline__ uint32_t swoff(int row, int seg) {
    return (uint32_t)row * 32 + ((seg ^ ((row >> 2) & 1)) << 4);
}

#define TILE16B 4096                     // 128 x 32B
#define STAGEB  (4 * TILE16B)            // 16KB per stage (Ah,Al,Bh,Bl)
// 3 stages = 48KB exactly (static smem ceiling)
struct MmaSmem { char buf[3][4][TILE16B]; };

__device__ __forceinline__ void cp_tile16(uint32_t sdst, const __nv_bfloat16* g,
                                          size_t ld, int row0, int k0) {
    const int t = threadIdx.x;
    const int row = t >> 1;
    const int seg = t & 1;
    const char* src = reinterpret_cast<const char*>(g + (size_t)(row0 + row) * ld + k0 + seg * 8);
    cp16(sdst + swoff(row, seg), src);
}

__device__ __forceinline__ void load_stage16(uint32_t sb,
    const __nv_bfloat16* Ah, const __nv_bfloat16* Al, size_t lda, int m0,
    const __nv_bfloat16* Bh, const __nv_bfloat16* Bl, size_t ldb, int n0, int k0)
{
    cp_tile16(sb,               Ah, lda, m0, k0);
    cp_tile16(sb + TILE16B,     Al, lda, m0, k0);
    cp_tile16(sb + 2 * TILE16B, Bh, ldb, n0, k0);
    cp_tile16(sb + 3 * TILE16B, Bl, ldb, n0, k0);
}

// one k=16 slice: acc += Ah*Bh + Ah*Bl + Al*Bh   (warp tile 32x64)
// term-major ordering per ntp group: same-acc reuse distance 4 (was 1)
__device__ __forceinline__ void compute_stage16(uint32_t sb, float acc[2][8][4],
                                                int lane, int wm, int wn)
{
    const uint32_t sAh = sb, sAl = sb + TILE16B, sBh = sb + 2 * TILE16B, sBl = sb + 3 * TILE16B;
    uint32_t ah[2][4], al[2][4];
    const int aseg = lane >> 4;
#pragma unroll
    for (int mt = 0; mt < 2; ++mt) {
        const int arow = wm * 32 + mt * 16 + (lane & 15);
        ldsm_x4(sAh + swoff(arow, aseg), ah[mt]);
        ldsm_x4(sAl + swoff(arow, aseg), al[mt]);
    }
    const int brow_in = ((lane >> 4) << 3) + (lane & 7);
    const int bseg = (lane >> 3) & 1;
#pragma unroll
    for (int ntp = 0; ntp < 4; ++ntp) {
        const int brow = wn * 64 + ntp * 16 + brow_in;
        uint32_t bh[4], bl[4];
        ldsm_x4(sBh + swoff(brow, bseg), bh);
        ldsm_x4(sBl + swoff(brow, bseg), bl);
        // term hh: 4 independent acc chains
#pragma unroll
        for (int mt = 0; mt < 2; ++mt)
#pragma unroll
            for (int h = 0; h < 2; ++h)
                mma16816(acc[mt][ntp * 2 + h], ah[mt], bh + h * 2);
        // term hl
#pragma unroll
        for (int mt = 0; mt < 2; ++mt)
#pragma unroll
            for (int h = 0; h < 2; ++h)
                mma16816(acc[mt][ntp * 2 + h], ah[mt], bl + h * 2);
        // term lh
#pragma unroll
        for (int mt = 0; mt < 2; ++mt)
#pragma unroll
            for (int h = 0; h < 2; ++h)
                mma16816(acc[mt][ntp * 2 + h], al[mt], bh + h * 2);
    }
}

// one pipeline step: wait for stage s, prefetch stage s+2 into pbase, compute stage s
__device__ __forceinline__ void pipe_step(int s, int nk, uint32_t cbase, uint32_t pbase,
    const __nv_bfloat16* Ah, const __nv_bfloat16* Al, size_t lda, int m0,
    const __nv_bfloat16* Bh, const __nv_bfloat16* Bl, size_t ldb, int n0,
    float acc[2][8][4], int lane, int wm, int wn)
{
    if (s >= nk) return;
    if (s + 1 < nk) CP_WAIT1(); else CP_WAIT0();
    __syncthreads();   // stage-s data visible AND all warps done computing stage s-1
    if (s + 2 < nk) {
        load_stage16(pbase, Ah, Al, lda, m0, Bh, Bl, ldb, n0, (s + 2) * 16);
        CP_COMMIT();
    }
    compute_stage16(cbase, acc, lane, wm, wn);
}

// C[128x128] = A[m0..+128, :k] * B[n0..+128, :k]^T (both [row][k], 3-term hi/lo)
// 3-stage pipeline, compile-time buffer indices, one barrier per chunk
__device__ __forceinline__ void gemm_hilo(uint32_t sb0,
    const __nv_bfloat16* Ah, const __nv_bfloat16* Al, size_t lda, int m0,
    const __nv_bfloat16* Bh, const __nv_bfloat16* Bl, size_t ldb, int n0,
    int kTotal, float acc[2][8][4])
{
    const int lane = threadIdx.x & 31;
    const int w = threadIdx.x >> 5;
    const int wm = w & 3, wn = w >> 2;
    const int nk = kTotal / 16;
    const uint32_t b0 = sb0, b1 = sb0 + STAGEB, b2 = sb0 + 2 * STAGEB;

    load_stage16(b0, Ah, Al, lda, m0, Bh, Bl, ldb, n0, 0);
    CP_COMMIT();
    if (nk > 1) {
        load_stage16(b1, Ah, Al, lda, m0, Bh, Bl, ldb, n0, 16);
        CP_COMMIT();
    }
    for (int s0 = 0; s0 < nk; s0 += 3) {
        pipe_step(s0 + 0, nk, b0, b2, Ah, Al, lda, m0, Bh, Bl, ldb, n0, acc, lane, wm, wn);
        pipe_step(s0 + 1, nk, b1, b0, Ah, Al, lda, m0, Bh, Bl, ldb, n0, acc, lane, wm, wn);
        pipe_step(s0 + 2, nk, b2, b1, Ah, Al, lda, m0, Bh, Bl, ldb, n0, acc, lane, wm, wn);
    }
}

__device__ __forceinline__ void split_hilo(float v, __nv_bfloat16& h, __nv_bfloat16& l) {
    h = __float2bfloat16_rn(v);
    l = __float2bfloat16_rn(v - __bfloat162float(h));
}

// ---------------- kernel 0: weight standardization (all 3 convs in one launch) ----------------
__global__ __launch_bounds__(256) void k_ws(const float* __restrict__ wq,
                                            const float* __restrict__ gq,
                                            const float* __restrict__ wk,
                                            const float* __restrict__ gk,
                                            const float* __restrict__ wv,
                                            const float* __restrict__ gv)
{
    const int which = blockIdx.y;
    const float* __restrict__ w    = (which == 0) ? wq : (which == 1) ? wk : wv;
    const float* __restrict__ gain = (which == 0) ? gq : (which == 1) ? gk : gv;

    const int o = blockIdx.x;
    const int t = threadIdx.x;
    const float v = w[o * CH + t];
    float s = v, ss = v * v;
#pragma unroll
    for (int off = 16; off; off >>= 1) {
        s  += __shfl_xor_sync(0xFFFFFFFFu, s,  off);
        ss += __shfl_xor_sync(0xFFFFFFFFu, ss, off);
    }
    __shared__ float sh_s[8], sh_ss[8], sh_scale, sh_msc;
    if ((t & 31) == 0) { sh_s[t >> 5] = s; sh_ss[t >> 5] = ss; }
    __syncthreads();
    if (t == 0) {
        float S = 0.f, SS = 0.f;
#pragma unroll
        for (int k = 0; k < 8; ++k) { S += sh_s[k]; SS += sh_ss[k]; }
        float mean = S * (1.0f / CH);
        float var  = (SS - (float)CH * mean * mean) * (1.0f / (CH - 1));
        float scale = rsqrtf(fmaxf(var * (float)CH, 1e-4f)) * gain[o];
        sh_scale = scale;
        sh_msc   = mean * scale;
    }
    __syncthreads();
    const float wn = v * sh_scale - sh_msc;
    __nv_bfloat16 h, l;
    split_hilo(wn, h, l);
    g_wn_hi[which][o * CH + t] = h;
    g_wn_lo[which][o * CH + t] = l;
}

// ---------------- kernel 1: transpose+split both a and b in one launch ----------------
__global__ __launch_bounds__(256) void k_split(const float* __restrict__ aIn,
                                               const float* __restrict__ bIn)
{
    __shared__ float t[64][65];
    const int which = blockIdx.z >> 2;
    const int batch = blockIdx.z & 3;
    const int hw0 = blockIdx.x * 64;
    const int c0  = blockIdx.y * 64;
    const float* __restrict__ src = (which ? bIn : aIn) + (size_t)batch * CH * HWN;
    const int tid = threadIdx.x;

    const int lr = tid >> 6;
    const int lc = tid & 63;
#pragma unroll
    for (int i = 0; i < 16; ++i) {
        const int r = i * 4 + lr;
        t[r][lc] = src[(size_t)(c0 + r) * HWN + hw0 + lc];
    }
    __syncthreads();

    __nv_bfloat16* __restrict__ H = xT_ptr(which, 0) + (size_t)batch * HWN * CH;
    __nv_bfloat16* __restrict__ L = xT_ptr(which, 1) + (size_t)batch * HWN * CH;
    const int wr = tid >> 5;
    const int wc = (tid & 31) * 2;
#pragma unroll
    for (int i = 0; i < 8; ++i) {
        const int r = i * 8 + wr;
        float v0 = t[wc][r], v1 = t[wc + 1][r];
        __nv_bfloat16 h0, l0, h1, l1;
        split_hilo(v0, h0, l0);
        split_hilo(v1, h1, l1);
        const size_t o = (size_t)(hw0 + r) * CH + c0 + wc;
        *reinterpret_cast<__nv_bfloat162*>(&H[o]) = __nv_bfloat162(h0, h1);
        *reinterpret_cast<__nv_bfloat162*>(&L[o]) = __nv_bfloat162(l0, l1);
    }
}

// ---------------- kernel 2: v = wn @ aT^T (mma), out [c][hw] hi/lo ----------------
__global__ __launch_bounds__(256) void k_v_mma(const float* __restrict__ bv)
{
    __shared__ __align__(1024) MmaSmem sm;
    const uint32_t sb0 = smem_u32(&sm);

    const int batch = blockIdx.z;
    const size_t xoff = (size_t)batch * HWN * CH;
    const size_t voff = (size_t)batch * CH * HWN;

    const int m0 = blockIdx.y * 128;   // c
    const int n0 = blockIdx.x * 128;   // hw

    float acc[2][8][4] = {};
    gemm_hilo(sb0, g_wn_hi[2], g_wn_lo[2], CH, m0,
              xT_ptr(0, 0) + xoff, xT_ptr(0, 1) + xoff, CH, n0, CH, acc);

    const int lane = threadIdx.x & 31;
    const int w = threadIdx.x >> 5;
    const int wm = w & 3, wn = w >> 2;
    const int gm_base = m0 + wm * 32 + (lane >> 2);
    const int gn_base = n0 + wn * 64 + (lane & 3) * 2;
#pragma unroll
    for (int mt = 0; mt < 2; ++mt) {
#pragma unroll
        for (int nt = 0; nt < 8; ++nt) {
            const int gn = gn_base + nt * 8;
#pragma unroll
            for (int half = 0; half < 2; ++half) {
                const int gm = gm_base + mt * 16 + half * 8;
                const float bb = bv[gm];
                float v0 = acc[mt][nt][half * 2 + 0] + bb;
                float v1 = acc[mt][nt][half * 2 + 1] + bb;
                __nv_bfloat16 h0, l0, h1, l1;
                split_hilo(v0, h0, l0);
                split_hilo(v1, h1, l1);
                const size_t o = voff + (size_t)gm * HWN + gn;
                *reinterpret_cast<__nv_bfloat162*>(&g_v_hi[o]) = __nv_bfloat162(h0, h1);
                *reinterpret_cast<__nv_bfloat162*>(&g_v_lo[o]) = __nv_bfloat162(l0, l1);
            }
        }
    }
}

// ---------------- kernel 3: qT/kT = xT @ wn^T (mma), out [hw][c] hi/lo ----------------
__global__ __launch_bounds__(256) void k_qk_mma(const float* __restrict__ bq,
                                                const float* __restrict__ bk)
{
    __shared__ __align__(1024) MmaSmem sm;
    const uint32_t sb0 = smem_u32(&sm);

    const int which = blockIdx.z >> 2;
    const int batch = blockIdx.z & 3;
    const size_t xoff = (size_t)batch * HWN * CH;
    const __nv_bfloat16* Xh = xT_ptr(which, 0) + xoff;
    const __nv_bfloat16* Xl = xT_ptr(which, 1) + xoff;
    const __nv_bfloat16* Wh = g_wn_hi[which];
    const __nv_bfloat16* Wl = g_wn_lo[which];
    const float* __restrict__ bias = which ? bk : bq;
    __nv_bfloat16* __restrict__ Hi = (which ? g_kT_hi : g_qT_hi) + xoff;
    __nv_bfloat16* __restrict__ Lo = (which ? g_kT_lo : g_qT_lo) + xoff;

    const int m0 = blockIdx.y * 128;   // hw
    const int n0 = blockIdx.x * 128;   // co

    float acc[2][8][4] = {};
    gemm_hilo(sb0, Xh, Xl, CH, m0, Wh, Wl, CH, n0, CH, acc);

    const int lane = threadIdx.x & 31;
    const int w = threadIdx.x >> 5;
    const int wm = w & 3, wn = w >> 2;
    const int gm_base = m0 + wm * 32 + (lane >> 2);
    const int gn_base = n0 + wn * 64 + (lane & 3) * 2;
#pragma unroll
    for (int mt = 0; mt < 2; ++mt) {
#pragma unroll
        for (int nt = 0; nt < 8; ++nt) {
            const int gn = gn_base + nt * 8;
            const float b0 = bias[gn], b1 = bias[gn + 1];
#pragma unroll
            for (int half = 0; half < 2; ++half) {
                const int gm = gm_base + mt * 16 + half * 8;
                float v0 = acc[mt][nt][half * 2 + 0] + b0;
                float v1 = acc[mt][nt][half * 2 + 1] + b1;
                __nv_bfloat16 h0, l0, h1, l1;
                split_hilo(v0, h0, l0);
                split_hilo(v1, h1, l1);
                const size_t o = (size_t)gm * CH + gn;
                *reinterpret_cast<__nv_bfloat162*>(&Hi[o]) = __nv_bfloat162(h0, h1);
                *reinterpret_cast<__nv_bfloat162*>(&Lo[o]) = __nv_bfloat162(l0, l1);
            }
        }
    }
}

// ---------------- kernel 4: sim = qT @ kT^T (mma.sync) ----------------
__global__ __launch_bounds__(256) void k_sim_mma()
{
    __shared__ __align__(1024) MmaSmem sm;
    const uint32_t sb0 = smem_u32(&sm);

    const int batch = blockIdx.z;
    const int m0 = blockIdx.y * 128;
    const int n0 = blockIdx.x * 128;
    const size_t boff = (size_t)batch * HWN * CH;

    float acc[2][8][4] = {};
    gemm_hilo(sb0, g_qT_hi + boff, g_qT_lo + boff, CH, m0,
              g_kT_hi + boff, g_kT_lo + boff, CH, n0, CH, acc);

    float* __restrict__ S = g_sim + (size_t)batch * HWN * HWN;
    const int lane = threadIdx.x & 31;
    const int w = threadIdx.x >> 5;
    const int wm = w & 3, wn = w >> 2;
    const int gm_base = m0 + wm * 32 + (lane >> 2);
    const int gn_base = n0 + wn * 64 + (lane & 3) * 2;
#pragma unroll
    for (int mt = 0; mt < 2; ++mt) {
#pragma unroll
        for (int nt = 0; nt < 8; ++nt) {
            const int gm = gm_base + mt * 16;
            const int gn = gn_base + nt * 8;
            float2 p0 = {acc[mt][nt][0], acc[mt][nt][1]};
            float2 p1 = {acc[mt][nt][2], acc[mt][nt][3]};
            *reinterpret_cast<float2*>(&S[(size_t)gm * HWN + gn]) = p0;
            *reinterpret_cast<float2*>(&S[(size_t)(gm + 8) * HWN + gn]) = p1;
        }
    }
}

// ---------------- kernel 5: masked softmax -> att bf16 hi/lo ----------------
__global__ __launch_bounds__(256) void k_softmax(const float* __restrict__ cIn)
{
    const int i = blockIdx.x;
    const int batch = blockIdx.y;
    const float* __restrict__ row = g_sim + ((size_t)batch * HWN + i) * HWN;
    __nv_bfloat16* __restrict__ Hi = g_att_hi + ((size_t)batch * HWN + i) * HWN;
    __nv_bfloat16* __restrict__ Lo = g_att_lo + ((size_t)batch * HWN + i) * HWN;

    const int h = i >> 6, w = i & 63;
    const float m = cIn[batch * MASKN + (h >> 1) * 32 + (w >> 1)];

    const int tid = threadIdx.x;
    float x[16];
    float vmax = -CUDART_INF_F;
#pragma unroll
    for (int p = 0; p < 4; ++p) {
        float4 v = *reinterpret_cast<const float4*>(&row[(p * 256 + tid) * 4]);
        x[p * 4 + 0] = m * v.x; x[p * 4 + 1] = m * v.y;
        x[p * 4 + 2] = m * v.z; x[p * 4 + 3] = m * v.w;
#pragma unroll
        for (int q = 0; q < 4; ++q) vmax = fmaxf(vmax, x[p * 4 + q]);
    }

    __shared__ float redm[8], reds[8], sh_max, sh_sum;
#pragma unroll
    for (int off = 16; off; off >>= 1) vmax = fmaxf(vmax, __shfl_xor_sync(0xFFFFFFFFu, vmax, off));
    if ((tid & 31) == 0) redm[tid >> 5] = vmax;
    __syncthreads();
    if (tid == 0) {
        float v = redm[0];
#pragma unroll
        for (int k = 1; k < 8; ++k) v = fmaxf(v, redm[k]);
        sh_max = v;
    }
    __syncthreads();
    const float M = sh_max;

    float total = 0.f;
#pragma unroll
    for (int q = 0; q < 16; ++q) {
        float e = __expf(x[q] - M);
        x[q] = e;
        total += e;
    }
#pragma unroll
    for (int off = 16; off; off >>= 1) total += __shfl_xor_sync(0xFFFFFFFFu, total, off);
    if ((tid & 31) == 0) reds[tid >> 5] = total;
    __syncthreads();
    if (tid == 0) {
        float v = 0.f;
#pragma unroll
        for (int k = 0; k < 8; ++k) v += reds[k];
        sh_sum = v;
    }
    __syncthreads();
    const float inv = 1.0f / sh_sum;

#pragma unroll
    for (int p = 0; p < 4; ++p) {
        const int idx = (p * 256 + tid) * 4;
#pragma unroll
        for (int q = 0; q < 4; q += 2) {
            float v0 = x[p * 4 + q] * inv;
            float v1 = x[p * 4 + q + 1] * inv;
            __nv_bfloat16 h0, l0, h1, l1;
            split_hilo(v0, h0, l0);
            split_hilo(v1, h1, l1);
            *reinterpret_cast<__nv_bfloat162*>(&Hi[idx + q]) = __nv_bfloat162(h0, h1);
            *reinterpret_cast<__nv_bfloat162*>(&Lo[idx + q]) = __nv_bfloat162(l0, l1);
        }
    }
}

// ---------------- kernel 6: out = v @ att^T (mma.sync), fused blend ----------------
__global__ __launch_bounds__(256) void k_pv_mma(const float* __restrict__ aIn,
                                                const float* __restrict__ cIn,
                                                const float* __restrict__ gammaPtr,
                                                float* __restrict__ out)
{
    __shared__ __align__(1024) MmaSmem sm;
    const uint32_t sb0 = smem_u32(&sm);

    const int batch = blockIdx.z;
    const int m0 = blockIdx.y * 128;   // channel
    const int n0 = blockIdx.x * 128;   // position i
    const size_t voff = (size_t)batch * CH * HWN;
    const size_t aoff = (size_t)batch * HWN * HWN;

    float acc[2][8][4] = {};
    gemm_hilo(sb0, g_v_hi + voff, g_v_lo + voff, HWN, m0,
              g_att_hi + aoff, g_att_lo + aoff, HWN, n0, HWN, acc);

    const float gamma = gammaPtr[0];
    const int lane = threadIdx.x & 31;
    const int w = threadIdx.x >> 5;
    const int wm = w & 3, wn = w >> 2;
    const int gm_base = m0 + wm * 32 + (lane >> 2);
    const int gn_base = n0 + wn * 64 + (lane & 3) * 2;

#pragma unroll
    for (int mt = 0; mt < 2; ++mt) {
#pragma unroll
        for (int nt = 0; nt < 8; ++nt) {
            const int gi = gn_base + nt * 8;
            const int hh = gi >> 6, ww = gi & 63;
            const float cr = cIn[batch * MASKN + (hh >> 1) * 32 + (ww >> 1)];
            const float gb = gamma * (1.0f - cr);
#pragma unroll
            for (int half = 0; half < 2; ++half) {
                const int gm = gm_base + mt * 16 + half * 8;
                const size_t base = ((size_t)batch * CH + gm) * HWN + gi;
                float2 av = *reinterpret_cast<const float2*>(&aIn[base]);
                float2 o;
                o.x = av.x * cr + gb * acc[mt][nt][half * 2 + 0];
                o.y = av.y * cr + gb * acc[mt][nt][half * 2 + 1];
                *reinterpret_cast<float2*>(&out[base]) = o;
            }
        }
    }
}

// ---------------- launch ----------------
extern "C" void kernel_launch(void* const* d_in, const int* in_sizes, int n_in,
                              void* d_out, int out_size)
{
    const float* a     = (const float*)d_in[0];
    const float* b     = (const float*)d_in[1];
    const float* cmask = (const float*)d_in[2];
    const float* wq    = (const float*)d_in[3];
    const float* bq    = (const float*)d_in[4];
    const float* gq    = (const float*)d_in[5];
    const float* wk    = (const float*)d_in[6];
    const float* bk    = (const float*)d_in[7];
    const float* gk    = (const float*)d_in[8];
    const float* wv    = (const float*)d_in[9];
    const float* bv    = (const float*)d_in[10];
    const float* gv    = (const float*)d_in[11];
    const float* gamma = (const float*)d_in[12];
    float* out = (float*)d_out;

    k_ws<<<dim3(CH, 3), 256>>>(wq, gq, wk, gk, wv, gv);          // launch 1

    dim3 gsp(HWN / 64, CH / 64, 8);
    k_split<<<gsp, 256>>>(a, b);                                  // launch 2

    dim3 gvv(HWN / 128, CH / 128, BATCH);
    k_v_mma<<<gvv, 256>>>(bv);                                    // launch 3

    dim3 gqk(CH / 128, HWN / 128, 8);
    k_qk_mma<<<gqk, 256>>>(bq, bk);                               // launch 4

    dim3 gsim(HWN / 128, HWN / 128, BATCH);
    k_sim_mma<<<gsim, 256>>>();                                   // launch 5

    k_softmax<<<dim3(HWN, BATCH), 256>>>(cmask);                  // launch 6

    dim3 gpv(HWN / 128, CH / 128, BATCH);
    k_pv_mma<<<gpv, 256>>>(a, cmask, gamma, out);                 // launch 7
}